// round 3
// baseline (speedup 1.0000x reference)
#include <cuda_runtime.h>
#include <math.h>

#define NB 4
#define SEQ 2048
#define EMB 1024
#define NH 16
#define HD 64
#define FFN 4096
#define NTOK (NB*SEQ)      // 8192
#define QKV_ROWS 4
#define ATT_SCALE 0.03125f // 1/sqrt(1024)

// ---------------- scratch (no allocations allowed) ----------------
__device__ float g_q[(size_t)NB*NH*SEQ*HD];
__device__ float g_k[(size_t)NB*NH*SEQ*HD];
__device__ float g_v[(size_t)NB*NH*SEQ*HD];
__device__ float g_ctx[(size_t)NTOK*EMB];
__device__ float g_attn[(size_t)NTOK*EMB];
__device__ float g_an[(size_t)NTOK*EMB];
__device__ float g_ff1[(size_t)NTOK*FFN];

__device__ __forceinline__ float warpSum(float v) {
#pragma unroll
    for (int o = 16; o > 0; o >>= 1) v += __shfl_xor_sync(0xffffffffu, v, o);
    return v;
}

// ---------------- kernel 1: LN1 + QKV projections (fused) ----------------
// grid = NTOK/QKV_ROWS blocks, 256 threads.
// dynamic smem: xs[QKV_ROWS][1024] + Ws[3][4096]  = 64KB
__global__ void ln_qkv_kernel(const float* __restrict__ x,
                              const float* __restrict__ Wq,
                              const float* __restrict__ Wk,
                              const float* __restrict__ Wv,
                              const float* __restrict__ lng,
                              const float* __restrict__ lnb,
                              float* __restrict__ q,
                              float* __restrict__ k,
                              float* __restrict__ v) {
    extern __shared__ float sm[];
    float* xs = sm;                       // QKV_ROWS * 1024
    float* Ws = sm + QKV_ROWS * EMB;      // 3 * 4096

    __shared__ float red1[8], red2[8];
    __shared__ float smu[QKV_ROWS], srs[QKV_ROWS];

    const int tid  = threadIdx.x;
    const int lane = tid & 31;
    const int warp = tid >> 5;
    const int row0 = blockIdx.x * QKV_ROWS;

    // weights into smem
    for (int i = tid; i < 4096; i += 256) {
        Ws[i]        = Wq[i];
        Ws[4096 + i] = Wk[i];
        Ws[8192 + i] = Wv[i];
    }

    // load rows + LN statistics
    for (int r = 0; r < QKV_ROWS; r++) {
        float4 val = ((const float4*)(x + (size_t)(row0 + r) * EMB))[tid];
        ((float4*)(xs + r * EMB))[tid] = val;
        float s1 = val.x + val.y + val.z + val.w;
        float s2 = val.x*val.x + val.y*val.y + val.z*val.z + val.w*val.w;
        s1 = warpSum(s1);
        s2 = warpSum(s2);
        if (lane == 0) { red1[warp] = s1; red2[warp] = s2; }
        __syncthreads();
        if (warp == 0) {
            float a = (lane < 8) ? red1[lane] : 0.f;
            float c = (lane < 8) ? red2[lane] : 0.f;
            a = warpSum(a);
            c = warpSum(c);
            if (lane == 0) {
                float mu  = a * (1.f / EMB);
                float var = c * (1.f / EMB) - mu * mu;
                smu[r] = mu;
                srs[r] = rsqrtf(var + 1e-5f);
            }
        }
        __syncthreads();
    }

    // normalize in smem (each thread touches only its own float4 slot)
    for (int r = 0; r < QKV_ROWS; r++) {
        float mu = smu[r], rs = srs[r];
        float4 val = ((float4*)(xs + r * EMB))[tid];
        float4 g4  = ((const float4*)lng)[tid];
        float4 b4  = ((const float4*)lnb)[tid];
        val.x = (val.x - mu) * rs * g4.x + b4.x;
        val.y = (val.y - mu) * rs * g4.y + b4.y;
        val.z = (val.z - mu) * rs * g4.z + b4.z;
        val.w = (val.w - mu) * rs * g4.w + b4.w;
        ((float4*)(xs + r * EMB))[tid] = val;
    }
    __syncthreads();

    // QKV: for each row, 3072 outputs (q|k|v interleaved by 'which')
    for (int r = 0; r < QKV_ROWS; r++) {
        const int R = row0 + r;
        const int n = R >> 11;        // / SEQ
        const int s = R & (SEQ - 1);
        for (int oo = tid; oo < 3072; oo += 256) {
            const int which = oo >> 10;
            const int h = (oo >> 6) & 15;
            const int d = oo & 63;
            const float* xv = xs + r * EMB + h * HD;
            const float* w  = Ws + which * 4096 + d;
            float a0 = 0.f, a1 = 0.f, a2 = 0.f, a3 = 0.f;
#pragma unroll
            for (int i = 0; i < 64; i += 4) {
                a0 += xv[i + 0] * w[(i + 0) * 64];
                a1 += xv[i + 1] * w[(i + 1) * 64];
                a2 += xv[i + 2] * w[(i + 2) * 64];
                a3 += xv[i + 3] * w[(i + 3) * 64];
            }
            float acc = (a0 + a1) + (a2 + a3);
            float* dst = (which == 0) ? q : (which == 1) ? k : v;
            dst[((((size_t)n * NH + h) * SEQ) + s) * HD + d] = acc;
        }
    }
}

// ---------------- kernel 2: flash-style attention ----------------
// q,k,v in [N,H,S,D]; ctx out in [N,S,H,D] (== [N,S,E] contiguous)
// 128 threads / block, 1 query per thread, K-tile = 64 keys
#define BQ 128
#define BK 64
__global__ void __launch_bounds__(128) attn_kernel(const float* __restrict__ q,
                                                   const float* __restrict__ k,
                                                   const float* __restrict__ v,
                                                   float* __restrict__ ctx) {
    __shared__ float Ks[BK][HD];
    __shared__ float Vs[BK][HD];

    const int tid = threadIdx.x;
    const int qt  = blockIdx.x & (SEQ / BQ - 1);   // 16 q-tiles
    const int nh  = blockIdx.x >> 4;               // n*H + h
    const int qi  = qt * BQ + tid;

    const float* qp = q + ((size_t)nh * SEQ + qi) * HD;
    float qr[HD];
#pragma unroll
    for (int i = 0; i < 16; i++) {
        float4 t4 = ((const float4*)qp)[i];
        qr[4*i+0] = t4.x * ATT_SCALE;
        qr[4*i+1] = t4.y * ATT_SCALE;
        qr[4*i+2] = t4.z * ATT_SCALE;
        qr[4*i+3] = t4.w * ATT_SCALE;
    }

    float acc[HD];
#pragma unroll
    for (int i = 0; i < HD; i++) acc[i] = 0.f;
    float m = -1e30f, l = 0.f;

    const float* kbase = k + (size_t)nh * SEQ * HD;
    const float* vbase = v + (size_t)nh * SEQ * HD;

    for (int t = 0; t < SEQ; t += BK) {
        __syncthreads();
        const float4* ksrc = (const float4*)(kbase + (size_t)t * HD);
        const float4* vsrc = (const float4*)(vbase + (size_t)t * HD);
        float4* kd = (float4*)&Ks[0][0];
        float4* vd = (float4*)&Vs[0][0];
#pragma unroll
        for (int i = 0; i < 8; i++) {
            kd[tid + 128 * i] = ksrc[tid + 128 * i];
            vd[tid + 128 * i] = vsrc[tid + 128 * i];
        }
        __syncthreads();

#pragma unroll 1
        for (int j = 0; j < BK; j++) {
            const float4* kro = (const float4*)&Ks[j][0];
            float s0 = 0.f, s1 = 0.f, s2 = 0.f, s3 = 0.f;
#pragma unroll
            for (int i = 0; i < 16; i++) {
                float4 kv = kro[i];
                s0 += qr[4*i+0] * kv.x;
                s1 += qr[4*i+1] * kv.y;
                s2 += qr[4*i+2] * kv.z;
                s3 += qr[4*i+3] * kv.w;
            }
            float s = (s0 + s1) + (s2 + s3);
            if (s > m) {
                float c = __expf(m - s);
                l *= c;
#pragma unroll
                for (int d2 = 0; d2 < HD; d2++) acc[d2] *= c;
                m = s;
            }
            float p = __expf(s - m);
            l += p;
            const float4* vro = (const float4*)&Vs[j][0];
#pragma unroll
            for (int i = 0; i < 16; i++) {
                float4 vv = vro[i];
                acc[4*i+0] += p * vv.x;
                acc[4*i+1] += p * vv.y;
                acc[4*i+2] += p * vv.z;
                acc[4*i+3] += p * vv.w;
            }
        }
    }

    const int n = nh >> 4, h = nh & 15;
    float* cp = ctx + (((size_t)(n * SEQ + qi)) * NH + h) * HD;
    const float inv = 1.f / l;
#pragma unroll
    for (int i = 0; i < 16; i++) {
        float4 o;
        o.x = acc[4*i+0] * inv;
        o.y = acc[4*i+1] * inv;
        o.z = acc[4*i+2] * inv;
        o.w = acc[4*i+3] * inv;
        ((float4*)cp)[i] = o;
    }
}

// ---------------- kernel 3/5/6: tiled SGEMM, fused epilogue ----------------
// C[M,N] = epilogue(A[M,K] @ B[K,N] + bias [+ res])
// 128x128 block tile, kTile=8, 256 threads, 8x8 per thread
__device__ __forceinline__ float gelu_exact(float x) {
    return 0.5f * x * (1.f + erff(x * 0.70710678118654752f));
}

template <bool GELU, bool RES>
__global__ void __launch_bounds__(256) gemm_kernel(const float* __restrict__ A,
                                                   const float* __restrict__ B,
                                                   const float* __restrict__ bias,
                                                   const float* __restrict__ res,
                                                   float* __restrict__ C,
                                                   int M, int N, int K) {
    __shared__ float As[8][128];
    __shared__ float Bs[8][128];

    const int tid = threadIdx.x;
    const int bm = blockIdx.y * 128;
    const int bn = blockIdx.x * 128;
    const int tx = tid & 15;
    const int ty = tid >> 4;

    const int arow = tid >> 1;
    const int acol = (tid & 1) * 4;
    const int brow = tid >> 5;
    const int bcol = (tid & 31) * 4;

    const float* Aptr = A + (size_t)(bm + arow) * K + acol;
    const float* Bptr = B + (size_t)brow * N + bn + bcol;

    float acc[8][8];
#pragma unroll
    for (int i = 0; i < 8; i++)
#pragma unroll
        for (int j = 0; j < 8; j++) acc[i][j] = 0.f;

    float4 av = *(const float4*)Aptr;
    float4 bv = *(const float4*)Bptr;

    for (int k0 = 8; ; k0 += 8) {
        As[acol + 0][arow] = av.x;
        As[acol + 1][arow] = av.y;
        As[acol + 2][arow] = av.z;
        As[acol + 3][arow] = av.w;
        *(float4*)&Bs[brow][bcol] = bv;
        __syncthreads();

        const bool more = (k0 < K);
        if (more) {
            Aptr += 8;
            Bptr += (size_t)8 * N;
            av = *(const float4*)Aptr;
            bv = *(const float4*)Bptr;
        }

#pragma unroll
        for (int kk = 0; kk < 8; kk++) {
            float a[8], b[8];
            *(float4*)(a + 0) = *(const float4*)&As[kk][ty * 8 + 0];
            *(float4*)(a + 4) = *(const float4*)&As[kk][ty * 8 + 4];
            *(float4*)(b + 0) = *(const float4*)&Bs[kk][tx * 8 + 0];
            *(float4*)(b + 4) = *(const float4*)&Bs[kk][tx * 8 + 4];
#pragma unroll
            for (int i = 0; i < 8; i++)
#pragma unroll
                for (int j = 0; j < 8; j++) acc[i][j] += a[i] * b[j];
        }
        __syncthreads();
        if (!more) break;
    }

    float bs[8];
#pragma unroll
    for (int j = 0; j < 8; j++) bs[j] = bias[bn + tx * 8 + j];

#pragma unroll
    for (int i = 0; i < 8; i++) {
        const size_t row = (size_t)(bm + ty * 8 + i);
        float* cp = C + row * N + bn + tx * 8;
        const float* rp = RES ? (res + row * N + bn + tx * 8) : nullptr;
#pragma unroll
        for (int j = 0; j < 8; j += 4) {
            float4 o;
            o.x = acc[i][j + 0] + bs[j + 0];
            o.y = acc[i][j + 1] + bs[j + 1];
            o.z = acc[i][j + 2] + bs[j + 2];
            o.w = acc[i][j + 3] + bs[j + 3];
            if (GELU) {
                o.x = gelu_exact(o.x);
                o.y = gelu_exact(o.y);
                o.z = gelu_exact(o.z);
                o.w = gelu_exact(o.w);
            }
            if (RES) {
                float4 r4 = *(const float4*)(rp + j);
                o.x += r4.x; o.y += r4.y; o.z += r4.z; o.w += r4.w;
            }
            *(float4*)(cp + j) = o;
        }
    }
}

// ---------------- kernel 4: LayerNorm (row per block) ----------------
__global__ void ln_kernel(const float* __restrict__ in,
                          const float* __restrict__ g,
                          const float* __restrict__ b,
                          float* __restrict__ out) {
    __shared__ float red1[8], red2[8];
    __shared__ float smu, srs;
    const int tid = threadIdx.x;
    const int lane = tid & 31, warp = tid >> 5;
    const size_t row = blockIdx.x;

    float4 val = ((const float4*)(in + row * EMB))[tid];
    float s1 = val.x + val.y + val.z + val.w;
    float s2 = val.x*val.x + val.y*val.y + val.z*val.z + val.w*val.w;
    s1 = warpSum(s1);
    s2 = warpSum(s2);
    if (lane == 0) { red1[warp] = s1; red2[warp] = s2; }
    __syncthreads();
    if (warp == 0) {
        float a = (lane < 8) ? red1[lane] : 0.f;
        float c = (lane < 8) ? red2[lane] : 0.f;
        a = warpSum(a);
        c = warpSum(c);
        if (lane == 0) {
            float mu = a * (1.f / EMB);
            float var = c * (1.f / EMB) - mu * mu;
            smu = mu;
            srs = rsqrtf(var + 1e-5f);
        }
    }
    __syncthreads();
    const float mu = smu, rs = srs;
    float4 g4 = ((const float4*)g)[tid];
    float4 b4 = ((const float4*)b)[tid];
    float4 o;
    o.x = (val.x - mu) * rs * g4.x + b4.x;
    o.y = (val.y - mu) * rs * g4.y + b4.y;
    o.z = (val.z - mu) * rs * g4.z + b4.z;
    o.w = (val.w - mu) * rs * g4.w + b4.w;
    ((float4*)(out + row * EMB))[tid] = o;
}

// ---------------- launch ----------------
extern "C" void kernel_launch(void* const* d_in, const int* in_sizes, int n_in,
                              void* d_out, int out_size) {
    const float* x    = (const float*)d_in[0];
    const float* Wq   = (const float*)d_in[1];
    const float* Wk   = (const float*)d_in[2];
    const float* Wv   = (const float*)d_in[3];
    const float* Wo   = (const float*)d_in[4];
    const float* bo   = (const float*)d_in[5];
    const float* ln1g = (const float*)d_in[6];
    const float* ln1b = (const float*)d_in[7];
    const float* ln2g = (const float*)d_in[8];
    const float* ln2b = (const float*)d_in[9];
    const float* W1   = (const float*)d_in[10];
    const float* b1   = (const float*)d_in[11];
    const float* W2   = (const float*)d_in[12];
    const float* b2   = (const float*)d_in[13];
    float* out = (float*)d_out;

    float *gq, *gk, *gv, *gctx, *gattn, *gan, *gff1;
    cudaGetSymbolAddress((void**)&gq,   g_q);
    cudaGetSymbolAddress((void**)&gk,   g_k);
    cudaGetSymbolAddress((void**)&gv,   g_v);
    cudaGetSymbolAddress((void**)&gctx, g_ctx);
    cudaGetSymbolAddress((void**)&gattn,g_attn);
    cudaGetSymbolAddress((void**)&gan,  g_an);
    cudaGetSymbolAddress((void**)&gff1, g_ff1);

    const int lnqkv_smem = (QKV_ROWS * EMB + 3 * 4096) * sizeof(float); // 64KB
    cudaFuncSetAttribute(ln_qkv_kernel, cudaFuncAttributeMaxDynamicSharedMemorySize, lnqkv_smem);

    // 1) LN1 + QKV
    ln_qkv_kernel<<<NTOK / QKV_ROWS, 256, lnqkv_smem>>>(x, Wq, Wk, Wv, ln1g, ln1b, gq, gk, gv);

    // 2) attention
    attn_kernel<<<NB * NH * (SEQ / BQ), 128>>>(gq, gk, gv, gctx);

    // 3) attn_out = x + ctx @ Wo + bo
    gemm_kernel<false, true><<<dim3(EMB / 128, NTOK / 128), 256>>>(
        gctx, Wo, bo, x, gattn, NTOK, EMB, EMB);

    // 4) LN2
    ln_kernel<<<NTOK, 256>>>(gattn, ln2g, ln2b, gan);

    // 5) ff1 = gelu(an @ W1 + b1)
    gemm_kernel<true, false><<<dim3(FFN / 128, NTOK / 128), 256>>>(
        gan, W1, b1, nullptr, gff1, NTOK, FFN, EMB);

    // 6) out = attn_out + ff1 @ W2 + b2
    gemm_kernel<false, true><<<dim3(EMB / 128, NTOK / 128), 256>>>(
        gff1, W2, b2, gattn, out, NTOK, EMB, FFN);
}

// round 4
// speedup vs baseline: 1.1346x; 1.1346x over previous
#include <cuda_runtime.h>
#include <math.h>

#define NB 4
#define SEQ 2048
#define EMB 1024
#define NH 16
#define HD 64
#define FFN 4096
#define NTOK (NB*SEQ)      // 8192
#define QKV_ROWS 8
#define ATT_SCALE 0.03125f // 1/sqrt(1024)

typedef unsigned long long u64;

// ---------------- f32x2 packed-math helpers (sm_103a FFMA2 path) ----------
__device__ __forceinline__ u64 fma2(u64 a, u64 b, u64 c) {
    u64 d;
    asm("fma.rn.f32x2 %0, %1, %2, %3;" : "=l"(d) : "l"(a), "l"(b), "l"(c));
    return d;
}
__device__ __forceinline__ u64 mul2(u64 a, u64 b) {
    u64 d;
    asm("mul.rn.f32x2 %0, %1, %2;" : "=l"(d) : "l"(a), "l"(b));
    return d;
}
__device__ __forceinline__ u64 add2(u64 a, u64 b) {
    u64 d;
    asm("add.rn.f32x2 %0, %1, %2;" : "=l"(d) : "l"(a), "l"(b));
    return d;
}
__device__ __forceinline__ u64 dup2(float x) {
    u64 d;
    asm("mov.b64 %0, {%1, %1};" : "=l"(d) : "f"(x));
    return d;
}
__device__ __forceinline__ u64 pack2(float lo, float hi) {
    u64 d;
    asm("mov.b64 %0, {%1, %2};" : "=l"(d) : "f"(lo), "f"(hi));
    return d;
}
__device__ __forceinline__ float2 unpk2(u64 v) {
    float2 r;
    asm("mov.b64 {%0, %1}, %2;" : "=f"(r.x), "=f"(r.y) : "l"(v));
    return r;
}
__device__ __forceinline__ u64 d2u(double x) { return __double_as_longlong(x); }

// ---------------- scratch (no allocations allowed) ----------------
__device__ float g_q[(size_t)NB*NH*SEQ*HD];
__device__ float g_k[(size_t)NB*NH*SEQ*HD];
__device__ float g_v[(size_t)NB*NH*SEQ*HD];
__device__ float g_ctx[(size_t)NTOK*EMB];
__device__ float g_attn[(size_t)NTOK*EMB];
__device__ float g_an[(size_t)NTOK*EMB];
__device__ float g_ff1[(size_t)NTOK*FFN];

__device__ __forceinline__ float warpSum(float v) {
#pragma unroll
    for (int o = 16; o > 0; o >>= 1) v += __shfl_xor_sync(0xffffffffu, v, o);
    return v;
}

// ---------------- kernel 1: LN1 + QKV projections (fused, f32x2) ----------
// grid = NTOK/QKV_ROWS blocks, 256 threads.
// dynamic smem: xs[8][1024] + Ws[3][4096] = 80KB
// Thread t handles column-pairs p = t and t+256 (p in [0,512)):
//   h = p>>5, d = (p&31)*2, computing outputs (d,d+1) of Q,K,V for all 8 rows.
__global__ void __launch_bounds__(256) ln_qkv_kernel(const float* __restrict__ x,
                              const float* __restrict__ Wq,
                              const float* __restrict__ Wk,
                              const float* __restrict__ Wv,
                              const float* __restrict__ lng,
                              const float* __restrict__ lnb,
                              float* __restrict__ q,
                              float* __restrict__ k,
                              float* __restrict__ v) {
    extern __shared__ float sm[];
    float* xs = sm;                       // QKV_ROWS * 1024
    float* Ws = sm + QKV_ROWS * EMB;      // 3 * 4096

    __shared__ float red1[8], red2[8];
    __shared__ float smu[QKV_ROWS], srs[QKV_ROWS];

    const int tid  = threadIdx.x;
    const int lane = tid & 31;
    const int warp = tid >> 5;
    const int row0 = blockIdx.x * QKV_ROWS;

    // weights into smem (vectorized)
    for (int i = tid; i < 1024; i += 256) {
        ((float4*)Ws)[i]        = ((const float4*)Wq)[i];
        ((float4*)Ws)[1024 + i] = ((const float4*)Wk)[i];
        ((float4*)Ws)[2048 + i] = ((const float4*)Wv)[i];
    }

    // load rows + LN statistics
    for (int r = 0; r < QKV_ROWS; r++) {
        float4 val = ((const float4*)(x + (size_t)(row0 + r) * EMB))[tid];
        ((float4*)(xs + r * EMB))[tid] = val;
        float s1 = val.x + val.y + val.z + val.w;
        float s2 = val.x*val.x + val.y*val.y + val.z*val.z + val.w*val.w;
        s1 = warpSum(s1);
        s2 = warpSum(s2);
        if (lane == 0) { red1[warp] = s1; red2[warp] = s2; }
        __syncthreads();
        if (warp == 0) {
            float a = (lane < 8) ? red1[lane] : 0.f;
            float c = (lane < 8) ? red2[lane] : 0.f;
            a = warpSum(a);
            c = warpSum(c);
            if (lane == 0) {
                float mu  = a * (1.f / EMB);
                float var = c * (1.f / EMB) - mu * mu;
                smu[r] = mu;
                srs[r] = rsqrtf(var + 1e-5f);
            }
        }
        __syncthreads();
    }

    // normalize in smem
    for (int r = 0; r < QKV_ROWS; r++) {
        float mu = smu[r], rs = srs[r];
        float4 val = ((float4*)(xs + r * EMB))[tid];
        float4 g4  = ((const float4*)lng)[tid];
        float4 b4  = ((const float4*)lnb)[tid];
        val.x = (val.x - mu) * rs * g4.x + b4.x;
        val.y = (val.y - mu) * rs * g4.y + b4.y;
        val.z = (val.z - mu) * rs * g4.z + b4.z;
        val.w = (val.w - mu) * rs * g4.w + b4.w;
        ((float4*)(xs + r * EMB))[tid] = val;
    }
    __syncthreads();

    // QKV projections: f32x2, weight pair reused across 8 rows & xv-dup across q/k/v
    for (int cc = 0; cc < 2; cc++) {
        const int p = tid + cc * 256;        // pair-column index [0,512)
        const int h = p >> 5;
        const int d = (p & 31) * 2;
        const float* xb = xs + h * HD;       // + r*EMB per row
        const float* wqp = Ws + d;
        const float* wkp = Ws + 4096 + d;
        const float* wvp = Ws + 8192 + d;

        u64 acc[3][QKV_ROWS];
#pragma unroll
        for (int w = 0; w < 3; w++)
#pragma unroll
            for (int r = 0; r < QKV_ROWS; r++) acc[w][r] = 0ull;

#pragma unroll 4
        for (int i = 0; i < 64; i++) {
            const u64 wq2 = *(const u64*)(wqp + i * 64);
            const u64 wk2 = *(const u64*)(wkp + i * 64);
            const u64 wv2 = *(const u64*)(wvp + i * 64);
#pragma unroll
            for (int r = 0; r < QKV_ROWS; r++) {
                const u64 ad = dup2(xb[r * EMB + i]);
                acc[0][r] = fma2(ad, wq2, acc[0][r]);
                acc[1][r] = fma2(ad, wk2, acc[1][r]);
                acc[2][r] = fma2(ad, wv2, acc[2][r]);
            }
        }

#pragma unroll
        for (int r = 0; r < QKV_ROWS; r++) {
            const int R = row0 + r;
            const int n = R >> 11;           // / SEQ
            const int s = R & (SEQ - 1);
            const size_t base = ((((size_t)n * NH + h) * SEQ) + s) * HD + d;
            float2 fq = unpk2(acc[0][r]);
            float2 fk = unpk2(acc[1][r]);
            float2 fv = unpk2(acc[2][r]);
            *(float2*)(q + base) = fq;
            *(float2*)(k + base) = fk;
            *(float2*)(v + base) = fv;
        }
    }
}

// ---------------- kernel 2: flash-style attention (f32x2) ----------------
#define BQ 128
#define BK 64
__global__ void __launch_bounds__(128, 3) attn_kernel(const float* __restrict__ q,
                                                   const float* __restrict__ k,
                                                   const float* __restrict__ v,
                                                   float* __restrict__ ctx) {
    __shared__ __align__(16) float Ks[BK][HD];
    __shared__ __align__(16) float Vs[BK][HD];

    const int tid = threadIdx.x;
    const int qt  = blockIdx.x & (SEQ / BQ - 1);   // 16 q-tiles
    const int nh  = blockIdx.x >> 4;               // n*H + h
    const int qi  = qt * BQ + tid;

    const float* qp = q + ((size_t)nh * SEQ + qi) * HD;
    u64 q2[32];
#pragma unroll
    for (int i = 0; i < 16; i++) {
        float4 t4 = ((const float4*)qp)[i];
        q2[2*i+0] = pack2(t4.x * ATT_SCALE, t4.y * ATT_SCALE);
        q2[2*i+1] = pack2(t4.z * ATT_SCALE, t4.w * ATT_SCALE);
    }

    u64 acc[32];
#pragma unroll
    for (int i = 0; i < 32; i++) acc[i] = 0ull;
    float m = -1e30f, l = 0.f;

    const float* kbase = k + (size_t)nh * SEQ * HD;
    const float* vbase = v + (size_t)nh * SEQ * HD;

    for (int t = 0; t < SEQ; t += BK) {
        __syncthreads();
        const float4* ksrc = (const float4*)(kbase + (size_t)t * HD);
        const float4* vsrc = (const float4*)(vbase + (size_t)t * HD);
        float4* kd = (float4*)&Ks[0][0];
        float4* vd = (float4*)&Vs[0][0];
#pragma unroll
        for (int i = 0; i < 8; i++) {
            kd[tid + 128 * i] = ksrc[tid + 128 * i];
            vd[tid + 128 * i] = vsrc[tid + 128 * i];
        }
        __syncthreads();

#pragma unroll 1
        for (int j = 0; j < BK; j++) {
            const double2* kp = (const double2*)&Ks[j][0];
            u64 s2[4] = {0ull, 0ull, 0ull, 0ull};
#pragma unroll
            for (int i = 0; i < 16; i++) {
                double2 kv = kp[i];
                s2[(2*i)   & 3] = fma2(q2[2*i],   d2u(kv.x), s2[(2*i)   & 3]);
                s2[(2*i+1) & 3] = fma2(q2[2*i+1], d2u(kv.y), s2[(2*i+1) & 3]);
            }
            u64 sc = add2(add2(s2[0], s2[1]), add2(s2[2], s2[3]));
            float2 sf = unpk2(sc);
            float s = sf.x + sf.y;

            if (s > m) {
                float c = __expf(m - s);
                l *= c;
                u64 cd = dup2(c);
#pragma unroll
                for (int d2i = 0; d2i < 32; d2i++) acc[d2i] = mul2(acc[d2i], cd);
                m = s;
            }
            float pw = __expf(s - m);
            l += pw;
            const u64 pd = dup2(pw);
            const double2* vp = (const double2*)&Vs[j][0];
#pragma unroll
            for (int i = 0; i < 16; i++) {
                double2 vv = vp[i];
                acc[2*i+0] = fma2(pd, d2u(vv.x), acc[2*i+0]);
                acc[2*i+1] = fma2(pd, d2u(vv.y), acc[2*i+1]);
            }
        }
    }

    const int n = nh >> 4, h = nh & 15;
    float* cp = ctx + (((size_t)(n * SEQ + qi)) * NH + h) * HD;
    const float inv = 1.f / l;
#pragma unroll
    for (int i = 0; i < 16; i++) {
        float2 p0 = unpk2(acc[2*i+0]);
        float2 p1 = unpk2(acc[2*i+1]);
        float4 o;
        o.x = p0.x * inv;
        o.y = p0.y * inv;
        o.z = p1.x * inv;
        o.w = p1.y * inv;
        ((float4*)cp)[i] = o;
    }
}

// ---------------- kernels 3/5/6: tiled SGEMM with f32x2 core --------------
// C[M,N] = epilogue(A[M,K] @ B[K,N] + bias [+ res])
// 128x256 block tile, kTile=8, 256 threads, 8x16 per thread.
// Thread columns: 4 chunks of 4 floats at bn + chunk*64 + tx*4 (conflict-free
// LDS.128, and each float4 = 2 f32x2 pairs directly via double2 bit-cast).
__device__ __forceinline__ float gelu_exact(float x) {
    return 0.5f * x * (1.f + erff(x * 0.70710678118654752f));
}

template <bool GELU, bool RES>
__global__ void __launch_bounds__(256, 1) gemm_kernel(const float* __restrict__ A,
                                                   const float* __restrict__ B,
                                                   const float* __restrict__ bias,
                                                   const float* __restrict__ res,
                                                   float* __restrict__ C,
                                                   int M, int N, int K) {
    __shared__ __align__(16) float As[8][128];
    __shared__ __align__(16) float Bs[8][256];

    const int tid = threadIdx.x;
    const int bm = blockIdx.y * 128;
    const int bn = blockIdx.x * 256;
    const int tx = tid & 15;     // 16 threads cover 256 cols (4 chunks x 4)
    const int ty = tid >> 4;     // 16 threads cover 128 rows (8 each)

    const int arow = tid >> 1;
    const int acol = (tid & 1) * 4;
    const int brow = tid >> 6;               // 0..3 (and +4 for 2nd vec)
    const int bcol = (tid & 63) * 4;

    const float* Aptr = A + (size_t)(bm + arow) * K + acol;
    const float* Bptr = B + (size_t)brow * N + bn + bcol;

    u64 acc[8][8];
#pragma unroll
    for (int i = 0; i < 8; i++)
#pragma unroll
        for (int j = 0; j < 8; j++) acc[i][j] = 0ull;

    float4 av  = *(const float4*)Aptr;
    float4 bv0 = *(const float4*)Bptr;
    float4 bv1 = *(const float4*)(Bptr + (size_t)4 * N);

    for (int k0 = 8; ; k0 += 8) {
        As[acol + 0][arow] = av.x;
        As[acol + 1][arow] = av.y;
        As[acol + 2][arow] = av.z;
        As[acol + 3][arow] = av.w;
        *(float4*)&Bs[brow][bcol]     = bv0;
        *(float4*)&Bs[brow + 4][bcol] = bv1;
        __syncthreads();

        const bool more = (k0 < K);
        if (more) {
            Aptr += 8;
            Bptr += (size_t)8 * N;
            av  = *(const float4*)Aptr;
            bv0 = *(const float4*)Bptr;
            bv1 = *(const float4*)(Bptr + (size_t)4 * N);
        }

#pragma unroll
        for (int kk = 0; kk < 8; kk++) {
            float a[8];
            *(float4*)(a + 0) = *(const float4*)&As[kk][ty * 8 + 0];
            *(float4*)(a + 4) = *(const float4*)&As[kk][ty * 8 + 4];
            u64 b2[8];
#pragma unroll
            for (int c = 0; c < 4; c++) {
                double2 t = *(const double2*)&Bs[kk][c * 64 + tx * 4];
                b2[c*2 + 0] = d2u(t.x);
                b2[c*2 + 1] = d2u(t.y);
            }
#pragma unroll
            for (int i = 0; i < 8; i++) {
                const u64 ad = dup2(a[i]);
#pragma unroll
                for (int j = 0; j < 8; j++) acc[i][j] = fma2(ad, b2[j], acc[i][j]);
            }
        }
        __syncthreads();
        if (!more) break;
    }

    float4 bsv[4];
#pragma unroll
    for (int c = 0; c < 4; c++)
        bsv[c] = *(const float4*)&bias[bn + c * 64 + tx * 4];

#pragma unroll
    for (int i = 0; i < 8; i++) {
        const size_t row = (size_t)(bm + ty * 8 + i);
        float* cp = C + row * N + bn;
        const float* rp = RES ? (res + row * N + bn) : nullptr;
#pragma unroll
        for (int c = 0; c < 4; c++) {
            const int col = c * 64 + tx * 4;
            float2 p0 = unpk2(acc[i][c*2 + 0]);
            float2 p1 = unpk2(acc[i][c*2 + 1]);
            float4 o;
            o.x = p0.x + bsv[c].x;
            o.y = p0.y + bsv[c].y;
            o.z = p1.x + bsv[c].z;
            o.w = p1.y + bsv[c].w;
            if (GELU) {
                o.x = gelu_exact(o.x);
                o.y = gelu_exact(o.y);
                o.z = gelu_exact(o.z);
                o.w = gelu_exact(o.w);
            }
            if (RES) {
                float4 r4 = *(const float4*)(rp + col);
                o.x += r4.x; o.y += r4.y; o.z += r4.z; o.w += r4.w;
            }
            *(float4*)(cp + col) = o;
        }
    }
}

// ---------------- kernel 4: LayerNorm (row per block) ----------------
__global__ void ln_kernel(const float* __restrict__ in,
                          const float* __restrict__ g,
                          const float* __restrict__ b,
                          float* __restrict__ out) {
    __shared__ float red1[8], red2[8];
    __shared__ float smu, srs;
    const int tid = threadIdx.x;
    const int lane = tid & 31, warp = tid >> 5;
    const size_t row = blockIdx.x;

    float4 val = ((const float4*)(in + row * EMB))[tid];
    float s1 = val.x + val.y + val.z + val.w;
    float s2 = val.x*val.x + val.y*val.y + val.z*val.z + val.w*val.w;
    s1 = warpSum(s1);
    s2 = warpSum(s2);
    if (lane == 0) { red1[warp] = s1; red2[warp] = s2; }
    __syncthreads();
    if (warp == 0) {
        float a = (lane < 8) ? red1[lane] : 0.f;
        float c = (lane < 8) ? red2[lane] : 0.f;
        a = warpSum(a);
        c = warpSum(c);
        if (lane == 0) {
            float mu = a * (1.f / EMB);
            float var = c * (1.f / EMB) - mu * mu;
            smu = mu;
            srs = rsqrtf(var + 1e-5f);
        }
    }
    __syncthreads();
    const float mu = smu, rs = srs;
    float4 g4 = ((const float4*)g)[tid];
    float4 b4 = ((const float4*)b)[tid];
    float4 o;
    o.x = (val.x - mu) * rs * g4.x + b4.x;
    o.y = (val.y - mu) * rs * g4.y + b4.y;
    o.z = (val.z - mu) * rs * g4.z + b4.z;
    o.w = (val.w - mu) * rs * g4.w + b4.w;
    ((float4*)(out + row * EMB))[tid] = o;
}

// ---------------- launch ----------------
extern "C" void kernel_launch(void* const* d_in, const int* in_sizes, int n_in,
                              void* d_out, int out_size) {
    const float* x    = (const float*)d_in[0];
    const float* Wq   = (const float*)d_in[1];
    const float* Wk   = (const float*)d_in[2];
    const float* Wv   = (const float*)d_in[3];
    const float* Wo   = (const float*)d_in[4];
    const float* bo   = (const float*)d_in[5];
    const float* ln1g = (const float*)d_in[6];
    const float* ln1b = (const float*)d_in[7];
    const float* ln2g = (const float*)d_in[8];
    const float* ln2b = (const float*)d_in[9];
    const float* W1   = (const float*)d_in[10];
    const float* b1   = (const float*)d_in[11];
    const float* W2   = (const float*)d_in[12];
    const float* b2   = (const float*)d_in[13];
    float* out = (float*)d_out;

    float *gq, *gk, *gv, *gctx, *gattn, *gan, *gff1;
    cudaGetSymbolAddress((void**)&gq,   g_q);
    cudaGetSymbolAddress((void**)&gk,   g_k);
    cudaGetSymbolAddress((void**)&gv,   g_v);
    cudaGetSymbolAddress((void**)&gctx, g_ctx);
    cudaGetSymbolAddress((void**)&gattn,g_attn);
    cudaGetSymbolAddress((void**)&gan,  g_an);
    cudaGetSymbolAddress((void**)&gff1, g_ff1);

    const int lnqkv_smem = (QKV_ROWS * EMB + 3 * 4096) * sizeof(float); // 80KB
    cudaFuncSetAttribute(ln_qkv_kernel, cudaFuncAttributeMaxDynamicSharedMemorySize, lnqkv_smem);

    // 1) LN1 + QKV
    ln_qkv_kernel<<<NTOK / QKV_ROWS, 256, lnqkv_smem>>>(x, Wq, Wk, Wv, ln1g, ln1b, gq, gk, gv);

    // 2) attention
    attn_kernel<<<NB * NH * (SEQ / BQ), 128>>>(gq, gk, gv, gctx);

    // 3) attn_out = x + ctx @ Wo + bo
    gemm_kernel<false, true><<<dim3(EMB / 256, NTOK / 128), 256>>>(
        gctx, Wo, bo, x, gattn, NTOK, EMB, EMB);

    // 4) LN2
    ln_kernel<<<NTOK, 256>>>(gattn, ln2g, ln2b, gan);

    // 5) ff1 = gelu(an @ W1 + b1)
    gemm_kernel<true, false><<<dim3(FFN / 256, NTOK / 128), 256>>>(
        gan, W1, b1, nullptr, gff1, NTOK, FFN, EMB);

    // 6) out = attn_out + ff1 @ W2 + b2
    gemm_kernel<false, true><<<dim3(EMB / 256, NTOK / 128), 256>>>(
        gff1, W2, b2, gattn, out, NTOK, EMB, FFN);
}

// round 7
// speedup vs baseline: 1.4693x; 1.2950x over previous
#include <cuda_runtime.h>
#include <math.h>
#include <stdint.h>

#define NB 4
#define SEQ 2048
#define EMB 1024
#define NH 16
#define HD 64
#define FFN 4096
#define NTOK (NB*SEQ)      // 8192
#define QKV_ROWS 8
#define ATT_SCALE 0.03125f // 1/sqrt(1024)

typedef unsigned long long u64;

// ---------------- f32x2 packed-math helpers ----------------
__device__ __forceinline__ u64 fma2(u64 a, u64 b, u64 c) {
    u64 d;
    asm("fma.rn.f32x2 %0, %1, %2, %3;" : "=l"(d) : "l"(a), "l"(b), "l"(c));
    return d;
}
__device__ __forceinline__ u64 mul2(u64 a, u64 b) {
    u64 d;
    asm("mul.rn.f32x2 %0, %1, %2;" : "=l"(d) : "l"(a), "l"(b));
    return d;
}
__device__ __forceinline__ u64 add2(u64 a, u64 b) {
    u64 d;
    asm("add.rn.f32x2 %0, %1, %2;" : "=l"(d) : "l"(a), "l"(b));
    return d;
}
__device__ __forceinline__ u64 dup2(float x) {
    u64 d;
    asm("mov.b64 %0, {%1, %1};" : "=l"(d) : "f"(x));
    return d;
}
__device__ __forceinline__ u64 pack2(float lo, float hi) {
    u64 d;
    asm("mov.b64 %0, {%1, %2};" : "=l"(d) : "f"(lo), "f"(hi));
    return d;
}
__device__ __forceinline__ float2 unpk2(u64 v) {
    float2 r;
    asm("mov.b64 {%0, %1}, %2;" : "=f"(r.x), "=f"(r.y) : "l"(v));
    return r;
}
__device__ __forceinline__ u64 d2u(double x) { return __double_as_longlong(x); }

__device__ __forceinline__ uint32_t tf32r(float x) {
    uint32_t y;
    asm("cvt.rna.tf32.f32 %0, %1;" : "=r"(y) : "f"(x));
    return y;
}

// ---------------- scratch (no allocations allowed) ----------------
__device__ float g_q[(size_t)NB*NH*SEQ*HD];
__device__ float g_k[(size_t)NB*NH*SEQ*HD];
__device__ float g_v[(size_t)NB*NH*SEQ*HD];
__device__ float g_ctx[(size_t)NTOK*EMB];
__device__ float g_attn[(size_t)NTOK*EMB];
__device__ float g_an[(size_t)NTOK*EMB];
__device__ float g_ff1[(size_t)NTOK*FFN];
__device__ float g_wo_t[(size_t)EMB*EMB];
__device__ float g_w1_t[(size_t)FFN*EMB];
__device__ float g_w2_t[(size_t)EMB*FFN];

__device__ __forceinline__ float warpSum(float v) {
#pragma unroll
    for (int o = 16; o > 0; o >>= 1) v += __shfl_xor_sync(0xffffffffu, v, o);
    return v;
}

// ---------------- kernel 0: transpose B[K][N] -> Bt[N][K] ----------------
__global__ void transpose_kernel(const float* __restrict__ in, float* __restrict__ out,
                                 int R, int Ccols) {
    __shared__ float ts[32][33];
    const int cb = blockIdx.x * 32, rb = blockIdx.y * 32;
    const int tx = threadIdx.x, ty = threadIdx.y;   // 32 x 8
#pragma unroll
    for (int j = 0; j < 32; j += 8)
        ts[ty + j][tx] = in[(size_t)(rb + ty + j) * Ccols + cb + tx];
    __syncthreads();
#pragma unroll
    for (int j = 0; j < 32; j += 8)
        out[(size_t)(cb + ty + j) * R + rb + tx] = ts[tx][ty + j];
}

// ---------------- kernel 1: LN1 + QKV projections (fused, f32x2) ----------
__global__ void __launch_bounds__(256) ln_qkv_kernel(const float* __restrict__ x,
                              const float* __restrict__ Wq,
                              const float* __restrict__ Wk,
                              const float* __restrict__ Wv,
                              const float* __restrict__ lng,
                              const float* __restrict__ lnb,
                              float* __restrict__ q,
                              float* __restrict__ k,
                              float* __restrict__ v) {
    extern __shared__ float sm[];
    float* xs = sm;                       // QKV_ROWS * 1024
    float* Ws = sm + QKV_ROWS * EMB;      // 3 * 4096

    __shared__ float red1[8], red2[8];
    __shared__ float smu[QKV_ROWS], srs[QKV_ROWS];

    const int tid  = threadIdx.x;
    const int lane = tid & 31;
    const int warp = tid >> 5;
    const int row0 = blockIdx.x * QKV_ROWS;

    for (int i = tid; i < 1024; i += 256) {
        ((float4*)Ws)[i]        = ((const float4*)Wq)[i];
        ((float4*)Ws)[1024 + i] = ((const float4*)Wk)[i];
        ((float4*)Ws)[2048 + i] = ((const float4*)Wv)[i];
    }

    for (int r = 0; r < QKV_ROWS; r++) {
        float4 val = ((const float4*)(x + (size_t)(row0 + r) * EMB))[tid];
        ((float4*)(xs + r * EMB))[tid] = val;
        float s1 = val.x + val.y + val.z + val.w;
        float s2 = val.x*val.x + val.y*val.y + val.z*val.z + val.w*val.w;
        s1 = warpSum(s1);
        s2 = warpSum(s2);
        if (lane == 0) { red1[warp] = s1; red2[warp] = s2; }
        __syncthreads();
        if (warp == 0) {
            float a = (lane < 8) ? red1[lane] : 0.f;
            float c = (lane < 8) ? red2[lane] : 0.f;
            a = warpSum(a);
            c = warpSum(c);
            if (lane == 0) {
                float mu  = a * (1.f / EMB);
                float var = c * (1.f / EMB) - mu * mu;
                smu[r] = mu;
                srs[r] = rsqrtf(var + 1e-5f);
            }
        }
        __syncthreads();
    }

    for (int r = 0; r < QKV_ROWS; r++) {
        float mu = smu[r], rs = srs[r];
        float4 val = ((float4*)(xs + r * EMB))[tid];
        float4 g4  = ((const float4*)lng)[tid];
        float4 b4  = ((const float4*)lnb)[tid];
        val.x = (val.x - mu) * rs * g4.x + b4.x;
        val.y = (val.y - mu) * rs * g4.y + b4.y;
        val.z = (val.z - mu) * rs * g4.z + b4.z;
        val.w = (val.w - mu) * rs * g4.w + b4.w;
        ((float4*)(xs + r * EMB))[tid] = val;
    }
    __syncthreads();

    for (int cc = 0; cc < 2; cc++) {
        const int p = tid + cc * 256;
        const int h = p >> 5;
        const int d = (p & 31) * 2;
        const float* xb = xs + h * HD;
        const float* wqp = Ws + d;
        const float* wkp = Ws + 4096 + d;
        const float* wvp = Ws + 8192 + d;

        u64 acc[3][QKV_ROWS];
#pragma unroll
        for (int w = 0; w < 3; w++)
#pragma unroll
            for (int r = 0; r < QKV_ROWS; r++) acc[w][r] = 0ull;

#pragma unroll 4
        for (int i = 0; i < 64; i++) {
            const u64 wq2 = *(const u64*)(wqp + i * 64);
            const u64 wk2 = *(const u64*)(wkp + i * 64);
            const u64 wv2 = *(const u64*)(wvp + i * 64);
#pragma unroll
            for (int r = 0; r < QKV_ROWS; r++) {
                const u64 ad = dup2(xb[r * EMB + i]);
                acc[0][r] = fma2(ad, wq2, acc[0][r]);
                acc[1][r] = fma2(ad, wk2, acc[1][r]);
                acc[2][r] = fma2(ad, wv2, acc[2][r]);
            }
        }

#pragma unroll
        for (int r = 0; r < QKV_ROWS; r++) {
            const int R = row0 + r;
            const int n = R >> 11;
            const int s = R & (SEQ - 1);
            const size_t base = ((((size_t)n * NH + h) * SEQ) + s) * HD + d;
            float2 fq = unpk2(acc[0][r]);
            float2 fk = unpk2(acc[1][r]);
            float2 fv = unpk2(acc[2][r]);
            *(float2*)(q + base) = fq;
            *(float2*)(k + base) = fk;
            *(float2*)(v + base) = fv;
        }
    }
}

// ---------------- kernel 2: flash-style attention (f32x2) ----------------
#define BQ 128
#define BK 64
__global__ void __launch_bounds__(128, 3) attn_kernel(const float* __restrict__ q,
                                                   const float* __restrict__ k,
                                                   const float* __restrict__ v,
                                                   float* __restrict__ ctx) {
    __shared__ __align__(16) float Ks[BK][HD];
    __shared__ __align__(16) float Vs[BK][HD];

    const int tid = threadIdx.x;
    const int qt  = blockIdx.x & (SEQ / BQ - 1);
    const int nh  = blockIdx.x >> 4;
    const int qi  = qt * BQ + tid;

    const float* qp = q + ((size_t)nh * SEQ + qi) * HD;
    u64 q2[32];
#pragma unroll
    for (int i = 0; i < 16; i++) {
        float4 t4 = ((const float4*)qp)[i];
        q2[2*i+0] = pack2(t4.x * ATT_SCALE, t4.y * ATT_SCALE);
        q2[2*i+1] = pack2(t4.z * ATT_SCALE, t4.w * ATT_SCALE);
    }

    u64 acc[32];
#pragma unroll
    for (int i = 0; i < 32; i++) acc[i] = 0ull;
    float m = -1e30f, l = 0.f;

    const float* kbase = k + (size_t)nh * SEQ * HD;
    const float* vbase = v + (size_t)nh * SEQ * HD;

    for (int t = 0; t < SEQ; t += BK) {
        __syncthreads();
        const float4* ksrc = (const float4*)(kbase + (size_t)t * HD);
        const float4* vsrc = (const float4*)(vbase + (size_t)t * HD);
        float4* kd = (float4*)&Ks[0][0];
        float4* vd = (float4*)&Vs[0][0];
#pragma unroll
        for (int i = 0; i < 8; i++) {
            kd[tid + 128 * i] = ksrc[tid + 128 * i];
            vd[tid + 128 * i] = vsrc[tid + 128 * i];
        }
        __syncthreads();

#pragma unroll 1
        for (int j = 0; j < BK; j++) {
            const double2* kp = (const double2*)&Ks[j][0];
            u64 s2[4] = {0ull, 0ull, 0ull, 0ull};
#pragma unroll
            for (int i = 0; i < 16; i++) {
                double2 kv = kp[i];
                s2[(2*i)   & 3] = fma2(q2[2*i],   d2u(kv.x), s2[(2*i)   & 3]);
                s2[(2*i+1) & 3] = fma2(q2[2*i+1], d2u(kv.y), s2[(2*i+1) & 3]);
            }
            u64 sc = add2(add2(s2[0], s2[1]), add2(s2[2], s2[3]));
            float2 sf = unpk2(sc);
            float s = sf.x + sf.y;

            if (s > m) {
                float c = __expf(m - s);
                l *= c;
                u64 cd = dup2(c);
#pragma unroll
                for (int d2i = 0; d2i < 32; d2i++) acc[d2i] = mul2(acc[d2i], cd);
                m = s;
            }
            float pw = __expf(s - m);
            l += pw;
            const u64 pd = dup2(pw);
            const double2* vp = (const double2*)&Vs[j][0];
#pragma unroll
            for (int i = 0; i < 16; i++) {
                double2 vv = vp[i];
                acc[2*i+0] = fma2(pd, d2u(vv.x), acc[2*i+0]);
                acc[2*i+1] = fma2(pd, d2u(vv.y), acc[2*i+1]);
            }
        }
    }

    const int n = nh >> 4, h = nh & 15;
    float* cp = ctx + (((size_t)(n * SEQ + qi)) * NH + h) * HD;
    const float inv = 1.f / l;
#pragma unroll
    for (int i = 0; i < 16; i++) {
        float2 p0 = unpk2(acc[2*i+0]);
        float2 p1 = unpk2(acc[2*i+1]);
        float4 o;
        o.x = p0.x * inv;
        o.y = p0.y * inv;
        o.z = p1.x * inv;
        o.w = p1.y * inv;
        ((float4*)cp)[i] = o;
    }
}

// ---------------- mma.sync tf32 GEMM (portable PTX, tensor pipe) ----------
// C[M,N] = epi(A[M,K] @ Bt[N,K]^T + bias [+ res])
// BM=128, BN=128, BK=32, 256 threads (8 warps, 2M x 4N), warp tile 64x32.
// m16n8k8 tf32 fragments; smem staged fragment-packed for LDS.128/LDS.64.
__device__ __forceinline__ float gelu_exact(float x) {
    return 0.5f * x * (1.f + erff(x * 0.70710678118654752f));
}

__device__ __forceinline__ void mma_tf32(float* d, const uint32_t* a, const uint32_t* b) {
    asm volatile(
        "mma.sync.aligned.m16n8k8.row.col.f32.tf32.tf32.f32 "
        "{%0, %1, %2, %3}, {%4, %5, %6, %7}, {%8, %9}, {%0, %1, %2, %3};"
        : "+f"(d[0]), "+f"(d[1]), "+f"(d[2]), "+f"(d[3])
        : "r"(a[0]), "r"(a[1]), "r"(a[2]), "r"(a[3]), "r"(b[0]), "r"(b[1]));
}

template <bool GELU, bool RES>
__global__ void __launch_bounds__(256, 1) gemm_mma(const float* __restrict__ A,
                                                   const float* __restrict__ Bt,
                                                   const float* __restrict__ bias,
                                                   const float* __restrict__ res,
                                                   float* __restrict__ C,
                                                   int M, int N, int K) {
    // fragment-packed: As[(mt*4+ks)*32 + lane][4], Bs[(nt*4+ks)*32 + lane][2]
    __shared__ __align__(16) uint32_t As[4096];
    __shared__ __align__(16) uint32_t Bs[4096];

    const int tid  = threadIdx.x;
    const int wid  = tid >> 5;
    const int lane = tid & 31;
    const int wm = wid & 1;          // 2 warps along M
    const int wn = wid >> 1;         // 4 warps along N
    const int bm = blockIdx.y * 128;
    const int bn = blockIdx.x * 128;

    float acc[4][4][4];
#pragma unroll
    for (int i = 0; i < 4; i++)
#pragma unroll
        for (int j = 0; j < 4; j++)
#pragma unroll
            for (int e = 0; e < 4; e++) acc[i][j][e] = 0.f;

    // loader coordinates: 1024 float4 per tile / 256 threads = 4 each
    // q = tid + i*256 -> row r = q>>3, col4 c4 = (q&7)*4
    const int T = K >> 5;

    float4 pa[4], pb[4];
#pragma unroll
    for (int i = 0; i < 4; i++) {
        const int qd = tid + i * 256;
        const int r = qd >> 3, c4 = (qd & 7) << 2;
        pa[i] = *(const float4*)(A  + (size_t)(bm + r) * K + c4);
        pb[i] = *(const float4*)(Bt + (size_t)(bn + r) * K + c4);
    }

    for (int t = 0; ; t++) {
        // stage fragment-packed (with tf32 rounding)
#pragma unroll
        for (int i = 0; i < 4; i++) {
            const int qd = tid + i * 256;
            const int r = qd >> 3, c4 = (qd & 7) << 2;
            {   // A: mt=r>>4, rr=r&15 -> g=rr&7, hi=rr>>3; ks=c4>>3, ch=(c4&7)>>2
                const int mt = r >> 4, rr = r & 15;
                const int g = rr & 7, hi = rr >> 3;
                const int ks = c4 >> 3, ch = (c4 & 7) >> 2;
                const int f = hi + 2 * ch;
                uint32_t* base = &As[(((mt << 2) + ks) << 7) + (g << 4) + f];
                base[0]  = tf32r(pa[i].x);
                base[4]  = tf32r(pa[i].y);
                base[8]  = tf32r(pa[i].z);
                base[12] = tf32r(pa[i].w);
            }
            {   // B: nt=r>>3, nn=r&7; ks=c4>>3, f=(c4&7)>>2
                const int nt = r >> 3, nn = r & 7;
                const int ks = c4 >> 3, f = (c4 & 7) >> 2;
                uint32_t* base = &Bs[((((nt << 2) + ks) << 6) + (nn << 3)) + f];
                base[0] = tf32r(pb[i].x);
                base[2] = tf32r(pb[i].y);
                base[4] = tf32r(pb[i].z);
                base[6] = tf32r(pb[i].w);
            }
        }
        __syncthreads();

        const bool more = (t + 1 < T);
        if (more) {
#pragma unroll
            for (int i = 0; i < 4; i++) {
                const int qd = tid + i * 256;
                const int r = qd >> 3, c4 = (qd & 7) << 2;
                pa[i] = *(const float4*)(A  + (size_t)(bm + r) * K + (t + 1) * 32 + c4);
                pb[i] = *(const float4*)(Bt + (size_t)(bn + r) * K + (t + 1) * 32 + c4);
            }
        }

        // compute: 4 k-steps x (4 mt x 4 nt) m16n8k8
#pragma unroll
        for (int ks = 0; ks < 4; ks++) {
            uint32_t af[4][4], bf[4][2];
#pragma unroll
            for (int i = 0; i < 4; i++) {
                const int mt = (wm << 2) + i;
                *(uint4*)af[i] = *(const uint4*)&As[((((mt << 2) + ks) << 5) + lane) << 2];
            }
#pragma unroll
            for (int j = 0; j < 4; j++) {
                const int nt = (wn << 2) + j;
                *(uint2*)bf[j] = *(const uint2*)&Bs[((((nt << 2) + ks) << 5) + lane) << 1];
            }
#pragma unroll
            for (int i = 0; i < 4; i++)
#pragma unroll
                for (int j = 0; j < 4; j++)
                    mma_tf32(acc[i][j], af[i], bf[j]);
        }
        __syncthreads();
        if (!more) break;
    }

    // epilogue: warp tile rows bm + wm*64 + i*16 + {g, g+8}, cols bn + wn*32 + j*8 + 2*tg
    const int g  = lane >> 2;
    const int tg = lane & 3;
#pragma unroll
    for (int i = 0; i < 4; i++) {
#pragma unroll
        for (int half = 0; half < 2; half++) {
            const int row = bm + wm * 64 + i * 16 + g + half * 8;
            float* cp = C + (size_t)row * N;
            const float* rp = RES ? (res + (size_t)row * N) : nullptr;
#pragma unroll
            for (int j = 0; j < 4; j++) {
                const int col = bn + wn * 32 + j * 8 + tg * 2;
                float2 o;
                o.x = acc[i][j][half * 2 + 0] + bias[col + 0];
                o.y = acc[i][j][half * 2 + 1] + bias[col + 1];
                if (GELU) {
                    o.x = gelu_exact(o.x);
                    o.y = gelu_exact(o.y);
                }
                if (RES) {
                    const float2 r2 = *(const float2*)(rp + col);
                    o.x += r2.x;
                    o.y += r2.y;
                }
                *(float2*)(cp + col) = o;
            }
        }
    }
}

// ---------------- kernel 4: LayerNorm (row per block) ----------------
__global__ void ln_kernel(const float* __restrict__ in,
                          const float* __restrict__ g,
                          const float* __restrict__ b,
                          float* __restrict__ out) {
    __shared__ float red1[8], red2[8];
    __shared__ float smu, srs;
    const int tid = threadIdx.x;
    const int lane = tid & 31, warp = tid >> 5;
    const size_t row = blockIdx.x;

    float4 val = ((const float4*)(in + row * EMB))[tid];
    float s1 = val.x + val.y + val.z + val.w;
    float s2 = val.x*val.x + val.y*val.y + val.z*val.z + val.w*val.w;
    s1 = warpSum(s1);
    s2 = warpSum(s2);
    if (lane == 0) { red1[warp] = s1; red2[warp] = s2; }
    __syncthreads();
    if (warp == 0) {
        float a = (lane < 8) ? red1[lane] : 0.f;
        float c = (lane < 8) ? red2[lane] : 0.f;
        a = warpSum(a);
        c = warpSum(c);
        if (lane == 0) {
            float mu = a * (1.f / EMB);
            float var = c * (1.f / EMB) - mu * mu;
            smu = mu;
            srs = rsqrtf(var + 1e-5f);
        }
    }
    __syncthreads();
    const float mu = smu, rs = srs;
    float4 g4 = ((const float4*)g)[tid];
    float4 b4 = ((const float4*)b)[tid];
    float4 o;
    o.x = (val.x - mu) * rs * g4.x + b4.x;
    o.y = (val.y - mu) * rs * g4.y + b4.y;
    o.z = (val.z - mu) * rs * g4.z + b4.z;
    o.w = (val.w - mu) * rs * g4.w + b4.w;
    ((float4*)(out + row * EMB))[tid] = o;
}

// ---------------- launch ----------------
extern "C" void kernel_launch(void* const* d_in, const int* in_sizes, int n_in,
                              void* d_out, int out_size) {
    const float* x    = (const float*)d_in[0];
    const float* Wq   = (const float*)d_in[1];
    const float* Wk   = (const float*)d_in[2];
    const float* Wv   = (const float*)d_in[3];
    const float* Wo   = (const float*)d_in[4];
    const float* bo   = (const float*)d_in[5];
    const float* ln1g = (const float*)d_in[6];
    const float* ln1b = (const float*)d_in[7];
    const float* ln2g = (const float*)d_in[8];
    const float* ln2b = (const float*)d_in[9];
    const float* W1   = (const float*)d_in[10];
    const float* b1   = (const float*)d_in[11];
    const float* W2   = (const float*)d_in[12];
    const float* b2   = (const float*)d_in[13];
    float* out = (float*)d_out;

    float *gq, *gk, *gv, *gctx, *gattn, *gan, *gff1, *gwo, *gw1, *gw2;
    cudaGetSymbolAddress((void**)&gq,   g_q);
    cudaGetSymbolAddress((void**)&gk,   g_k);
    cudaGetSymbolAddress((void**)&gv,   g_v);
    cudaGetSymbolAddress((void**)&gctx, g_ctx);
    cudaGetSymbolAddress((void**)&gattn,g_attn);
    cudaGetSymbolAddress((void**)&gan,  g_an);
    cudaGetSymbolAddress((void**)&gff1, g_ff1);
    cudaGetSymbolAddress((void**)&gwo,  g_wo_t);
    cudaGetSymbolAddress((void**)&gw1,  g_w1_t);
    cudaGetSymbolAddress((void**)&gw2,  g_w2_t);

    const int lnqkv_smem = (QKV_ROWS * EMB + 3 * 4096) * sizeof(float); // 80KB
    cudaFuncSetAttribute(ln_qkv_kernel, cudaFuncAttributeMaxDynamicSharedMemorySize, lnqkv_smem);

    // 0) weight transposes: Bt[N][K] from B[K][N]
    transpose_kernel<<<dim3(EMB / 32, EMB / 32), dim3(32, 8)>>>(Wo, gwo, EMB, EMB);
    transpose_kernel<<<dim3(FFN / 32, EMB / 32), dim3(32, 8)>>>(W1, gw1, EMB, FFN);
    transpose_kernel<<<dim3(EMB / 32, FFN / 32), dim3(32, 8)>>>(W2, gw2, FFN, EMB);

    // 1) LN1 + QKV
    ln_qkv_kernel<<<NTOK / QKV_ROWS, 256, lnqkv_smem>>>(x, Wq, Wk, Wv, ln1g, ln1b, gq, gk, gv);

    // 2) attention
    attn_kernel<<<NB * NH * (SEQ / BQ), 128>>>(gq, gk, gv, gctx);

    // 3) attn_out = x + ctx @ Wo + bo            (tf32 mma.sync)
    gemm_mma<false, true><<<dim3(EMB / 128, NTOK / 128), 256>>>(
        gctx, gwo, bo, x, gattn, NTOK, EMB, EMB);

    // 4) LN2
    ln_kernel<<<NTOK, 256>>>(gattn, ln2g, ln2b, gan);

    // 5) ff1 = gelu(an @ W1 + b1)                (tf32 mma.sync)
    gemm_mma<true, false><<<dim3(FFN / 128, NTOK / 128), 256>>>(
        gan, gw1, b1, nullptr, gff1, NTOK, FFN, EMB);

    // 6) out = attn_out + ff1 @ W2 + b2          (tf32 mma.sync)
    gemm_mma<false, true><<<dim3(EMB / 128, NTOK / 128), 256>>>(
        gff1, gw2, b2, gattn, out, NTOK, EMB, FFN);
}

// round 11
// speedup vs baseline: 1.4708x; 1.0010x over previous
#include <cuda_runtime.h>
#include <math.h>
#include <stdint.h>

#define NB 4
#define SEQ 2048
#define EMB 1024
#define NH 16
#define HD 64
#define FFN 4096
#define NTOK (NB*SEQ)      // 8192
#define QKV_ROWS 8
#define ATT_SCALE 0.03125f // 1/sqrt(1024)

typedef unsigned long long u64;

// ---------------- f32x2 packed-math helpers ----------------
__device__ __forceinline__ u64 fma2(u64 a, u64 b, u64 c) {
    u64 d;
    asm("fma.rn.f32x2 %0, %1, %2, %3;" : "=l"(d) : "l"(a), "l"(b), "l"(c));
    return d;
}
__device__ __forceinline__ u64 mul2(u64 a, u64 b) {
    u64 d;
    asm("mul.rn.f32x2 %0, %1, %2;" : "=l"(d) : "l"(a), "l"(b));
    return d;
}
__device__ __forceinline__ u64 add2(u64 a, u64 b) {
    u64 d;
    asm("add.rn.f32x2 %0, %1, %2;" : "=l"(d) : "l"(a), "l"(b));
    return d;
}
__device__ __forceinline__ u64 dup2(float x) {
    u64 d;
    asm("mov.b64 %0, {%1, %1};" : "=l"(d) : "f"(x));
    return d;
}
__device__ __forceinline__ u64 pack2(float lo, float hi) {
    u64 d;
    asm("mov.b64 %0, {%1, %2};" : "=l"(d) : "f"(lo), "f"(hi));
    return d;
}
__device__ __forceinline__ float2 unpk2(u64 v) {
    float2 r;
    asm("mov.b64 {%0, %1}, %2;" : "=f"(r.x), "=f"(r.y) : "l"(v));
    return r;
}
__device__ __forceinline__ u64 d2u(double x) { return __double_as_longlong(x); }

__device__ __forceinline__ uint32_t tf32r(float x) {
    uint32_t y;
    asm("cvt.rna.tf32.f32 %0, %1;" : "=r"(y) : "f"(x));
    return y;
}

// ---------------- scratch (no allocations allowed) ----------------
__device__ float g_q[(size_t)NB*NH*SEQ*HD];
__device__ float g_k[(size_t)NB*NH*SEQ*HD];
__device__ float g_v[(size_t)NB*NH*SEQ*HD];
__device__ float g_ctx[(size_t)NTOK*EMB];
__device__ float g_attn[(size_t)NTOK*EMB];
__device__ float g_an[(size_t)NTOK*EMB];
__device__ float g_ff1[(size_t)NTOK*FFN];
__device__ float g_wo_t[(size_t)EMB*EMB];
__device__ float g_w1_t[(size_t)FFN*EMB];
__device__ float g_w2_t[(size_t)EMB*FFN];

__device__ __forceinline__ float warpSum(float v) {
#pragma unroll
    for (int o = 16; o > 0; o >>= 1) v += __shfl_xor_sync(0xffffffffu, v, o);
    return v;
}

// ---------------- kernel 0: transpose B[K][N] -> Bt[N][K] ----------------
__global__ void transpose_kernel(const float* __restrict__ in, float* __restrict__ out,
                                 int R, int Ccols) {
    __shared__ float ts[32][33];
    const int cb = blockIdx.x * 32, rb = blockIdx.y * 32;
    const int tx = threadIdx.x, ty = threadIdx.y;   // 32 x 8
#pragma unroll
    for (int j = 0; j < 32; j += 8)
        ts[ty + j][tx] = in[(size_t)(rb + ty + j) * Ccols + cb + tx];
    __syncthreads();
#pragma unroll
    for (int j = 0; j < 32; j += 8)
        out[(size_t)(cb + ty + j) * R + rb + tx] = ts[tx][ty + j];
}

// ---------------- kernel 1: LN1 + QKV projections (fused, f32x2) ----------
__global__ void __launch_bounds__(256) ln_qkv_kernel(const float* __restrict__ x,
                              const float* __restrict__ Wq,
                              const float* __restrict__ Wk,
                              const float* __restrict__ Wv,
                              const float* __restrict__ lng,
                              const float* __restrict__ lnb,
                              float* __restrict__ q,
                              float* __restrict__ k,
                              float* __restrict__ v) {
    extern __shared__ float sm[];
    float* xs = sm;                       // QKV_ROWS * 1024
    float* Ws = sm + QKV_ROWS * EMB;      // 3 * 4096

    __shared__ float red1[8], red2[8];
    __shared__ float smu[QKV_ROWS], srs[QKV_ROWS];

    const int tid  = threadIdx.x;
    const int lane = tid & 31;
    const int warp = tid >> 5;
    const int row0 = blockIdx.x * QKV_ROWS;

    for (int i = tid; i < 1024; i += 256) {
        ((float4*)Ws)[i]        = ((const float4*)Wq)[i];
        ((float4*)Ws)[1024 + i] = ((const float4*)Wk)[i];
        ((float4*)Ws)[2048 + i] = ((const float4*)Wv)[i];
    }

    for (int r = 0; r < QKV_ROWS; r++) {
        float4 val = ((const float4*)(x + (size_t)(row0 + r) * EMB))[tid];
        ((float4*)(xs + r * EMB))[tid] = val;
        float s1 = val.x + val.y + val.z + val.w;
        float s2 = val.x*val.x + val.y*val.y + val.z*val.z + val.w*val.w;
        s1 = warpSum(s1);
        s2 = warpSum(s2);
        if (lane == 0) { red1[warp] = s1; red2[warp] = s2; }
        __syncthreads();
        if (warp == 0) {
            float a = (lane < 8) ? red1[lane] : 0.f;
            float c = (lane < 8) ? red2[lane] : 0.f;
            a = warpSum(a);
            c = warpSum(c);
            if (lane == 0) {
                float mu  = a * (1.f / EMB);
                float var = c * (1.f / EMB) - mu * mu;
                smu[r] = mu;
                srs[r] = rsqrtf(var + 1e-5f);
            }
        }
        __syncthreads();
    }

    for (int r = 0; r < QKV_ROWS; r++) {
        float mu = smu[r], rs = srs[r];
        float4 val = ((float4*)(xs + r * EMB))[tid];
        float4 g4  = ((const float4*)lng)[tid];
        float4 b4  = ((const float4*)lnb)[tid];
        val.x = (val.x - mu) * rs * g4.x + b4.x;
        val.y = (val.y - mu) * rs * g4.y + b4.y;
        val.z = (val.z - mu) * rs * g4.z + b4.z;
        val.w = (val.w - mu) * rs * g4.w + b4.w;
        ((float4*)(xs + r * EMB))[tid] = val;
    }
    __syncthreads();

    for (int cc = 0; cc < 2; cc++) {
        const int p = tid + cc * 256;
        const int h = p >> 5;
        const int d = (p & 31) * 2;
        const float* xb = xs + h * HD;
        const float* wqp = Ws + d;
        const float* wkp = Ws + 4096 + d;
        const float* wvp = Ws + 8192 + d;

        u64 acc[3][QKV_ROWS];
#pragma unroll
        for (int w = 0; w < 3; w++)
#pragma unroll
            for (int r = 0; r < QKV_ROWS; r++) acc[w][r] = 0ull;

#pragma unroll 4
        for (int i = 0; i < 64; i++) {
            const u64 wq2 = *(const u64*)(wqp + i * 64);
            const u64 wk2 = *(const u64*)(wkp + i * 64);
            const u64 wv2 = *(const u64*)(wvp + i * 64);
#pragma unroll
            for (int r = 0; r < QKV_ROWS; r++) {
                const u64 ad = dup2(xb[r * EMB + i]);
                acc[0][r] = fma2(ad, wq2, acc[0][r]);
                acc[1][r] = fma2(ad, wk2, acc[1][r]);
                acc[2][r] = fma2(ad, wv2, acc[2][r]);
            }
        }

#pragma unroll
        for (int r = 0; r < QKV_ROWS; r++) {
            const int R = row0 + r;
            const int n = R >> 11;
            const int s = R & (SEQ - 1);
            const size_t base = ((((size_t)n * NH + h) * SEQ) + s) * HD + d;
            float2 fq = unpk2(acc[0][r]);
            float2 fk = unpk2(acc[1][r]);
            float2 fv = unpk2(acc[2][r]);
            *(float2*)(q + base) = fq;
            *(float2*)(k + base) = fk;
            *(float2*)(v + base) = fv;
        }
    }
}

// ---------------- kernel 2: flash-style attention (f32x2) ----------------
#define BQ 128
#define BK 64
__global__ void __launch_bounds__(128, 3) attn_kernel(const float* __restrict__ q,
                                                   const float* __restrict__ k,
                                                   const float* __restrict__ v,
                                                   float* __restrict__ ctx) {
    __shared__ __align__(16) float Ks[BK][HD];
    __shared__ __align__(16) float Vs[BK][HD];

    const int tid = threadIdx.x;
    const int qt  = blockIdx.x & (SEQ / BQ - 1);
    const int nh  = blockIdx.x >> 4;
    const int qi  = qt * BQ + tid;

    const float* qp = q + ((size_t)nh * SEQ + qi) * HD;
    u64 q2[32];
#pragma unroll
    for (int i = 0; i < 16; i++) {
        float4 t4 = ((const float4*)qp)[i];
        q2[2*i+0] = pack2(t4.x * ATT_SCALE, t4.y * ATT_SCALE);
        q2[2*i+1] = pack2(t4.z * ATT_SCALE, t4.w * ATT_SCALE);
    }

    u64 acc[32];
#pragma unroll
    for (int i = 0; i < 32; i++) acc[i] = 0ull;
    float m = -1e30f, l = 0.f;

    const float* kbase = k + (size_t)nh * SEQ * HD;
    const float* vbase = v + (size_t)nh * SEQ * HD;

    for (int t = 0; t < SEQ; t += BK) {
        __syncthreads();
        const float4* ksrc = (const float4*)(kbase + (size_t)t * HD);
        const float4* vsrc = (const float4*)(vbase + (size_t)t * HD);
        float4* kd = (float4*)&Ks[0][0];
        float4* vd = (float4*)&Vs[0][0];
#pragma unroll
        for (int i = 0; i < 8; i++) {
            kd[tid + 128 * i] = ksrc[tid + 128 * i];
            vd[tid + 128 * i] = vsrc[tid + 128 * i];
        }
        __syncthreads();

#pragma unroll 1
        for (int j = 0; j < BK; j++) {
            const double2* kp = (const double2*)&Ks[j][0];
            u64 s2[4] = {0ull, 0ull, 0ull, 0ull};
#pragma unroll
            for (int i = 0; i < 16; i++) {
                double2 kv = kp[i];
                s2[(2*i)   & 3] = fma2(q2[2*i],   d2u(kv.x), s2[(2*i)   & 3]);
                s2[(2*i+1) & 3] = fma2(q2[2*i+1], d2u(kv.y), s2[(2*i+1) & 3]);
            }
            u64 sc = add2(add2(s2[0], s2[1]), add2(s2[2], s2[3]));
            float2 sf = unpk2(sc);
            float s = sf.x + sf.y;

            if (s > m) {
                float c = __expf(m - s);
                l *= c;
                u64 cd = dup2(c);
#pragma unroll
                for (int d2i = 0; d2i < 32; d2i++) acc[d2i] = mul2(acc[d2i], cd);
                m = s;
            }
            float pw = __expf(s - m);
            l += pw;
            const u64 pd = dup2(pw);
            const double2* vp = (const double2*)&Vs[j][0];
#pragma unroll
            for (int i = 0; i < 16; i++) {
                double2 vv = vp[i];
                acc[2*i+0] = fma2(pd, d2u(vv.x), acc[2*i+0]);
                acc[2*i+1] = fma2(pd, d2u(vv.y), acc[2*i+1]);
            }
        }
    }

    const int n = nh >> 4, h = nh & 15;
    float* cp = ctx + (((size_t)(n * SEQ + qi)) * NH + h) * HD;
    const float inv = 1.f / l;
#pragma unroll
    for (int i = 0; i < 16; i++) {
        float2 p0 = unpk2(acc[2*i+0]);
        float2 p1 = unpk2(acc[2*i+1]);
        float4 o;
        o.x = p0.x * inv;
        o.y = p0.y * inv;
        o.z = p1.x * inv;
        o.w = p1.y * inv;
        ((float4*)cp)[i] = o;
    }
}

// ---------------- mma.sync tf32 GEMM (portable PTX, tensor pipe) ----------
// C[M,N] = epi(A[M,K] @ Bt[N,K]^T + bias [+ res])
// BM=128, BN=128, BK=32, 256 threads (8 warps, 2M x 4N), warp tile 64x32.
// m16n8k8 tf32 fragments; smem staged fragment-packed for LDS.128/LDS.64.
__device__ __forceinline__ float gelu_exact(float x) {
    return 0.5f * x * (1.f + erff(x * 0.70710678118654752f));
}

__device__ __forceinline__ void mma_tf32(float* d, const uint32_t* a, const uint32_t* b) {
    asm volatile(
        "mma.sync.aligned.m16n8k8.row.col.f32.tf32.tf32.f32 "
        "{%0, %1, %2, %3}, {%4, %5, %6, %7}, {%8, %9}, {%0, %1, %2, %3};"
        : "+f"(d[0]), "+f"(d[1]), "+f"(d[2]), "+f"(d[3])
        : "r"(a[0]), "r"(a[1]), "r"(a[2]), "r"(a[3]), "r"(b[0]), "r"(b[1]));
}

template <bool GELU, bool RES>
__global__ void __launch_bounds__(256, 1) gemm_mma(const float* __restrict__ A,
                                                   const float* __restrict__ Bt,
                                                   const float* __restrict__ bias,
                                                   const float* __restrict__ res,
                                                   float* __restrict__ C,
                                                   int M, int N, int K) {
    // fragment-packed: As[(mt*4+ks)*32 + lane][4], Bs[(nt*4+ks)*32 + lane][2]
    __shared__ __align__(16) uint32_t As[4096];
    __shared__ __align__(16) uint32_t Bs[4096];

    const int tid  = threadIdx.x;
    const int wid  = tid >> 5;
    const int lane = tid & 31;
    const int wm = wid & 1;          // 2 warps along M
    const int wn = wid >> 1;         // 4 warps along N
    const int bm = blockIdx.y * 128;
    const int bn = blockIdx.x * 128;

    float acc[4][4][4];
#pragma unroll
    for (int i = 0; i < 4; i++)
#pragma unroll
        for (int j = 0; j < 4; j++)
#pragma unroll
            for (int e = 0; e < 4; e++) acc[i][j][e] = 0.f;

    // loader coordinates: 1024 float4 per tile / 256 threads = 4 each
    // q = tid + i*256 -> row r = q>>3, col4 c4 = (q&7)*4
    const int T = K >> 5;

    float4 pa[4], pb[4];
#pragma unroll
    for (int i = 0; i < 4; i++) {
        const int qd = tid + i * 256;
        const int r = qd >> 3, c4 = (qd & 7) << 2;
        pa[i] = *(const float4*)(A  + (size_t)(bm + r) * K + c4);
        pb[i] = *(const float4*)(Bt + (size_t)(bn + r) * K + c4);
    }

    for (int t = 0; ; t++) {
        // stage fragment-packed (with tf32 rounding)
#pragma unroll
        for (int i = 0; i < 4; i++) {
            const int qd = tid + i * 256;
            const int r = qd >> 3, c4 = (qd & 7) << 2;
            {   // A: mt=r>>4, rr=r&15 -> g=rr&7, hi=rr>>3; ks=c4>>3, ch=(c4&7)>>2
                const int mt = r >> 4, rr = r & 15;
                const int g = rr & 7, hi = rr >> 3;
                const int ks = c4 >> 3, ch = (c4 & 7) >> 2;
                const int f = hi + 2 * ch;
                uint32_t* base = &As[(((mt << 2) + ks) << 7) + (g << 4) + f];
                base[0]  = tf32r(pa[i].x);
                base[4]  = tf32r(pa[i].y);
                base[8]  = tf32r(pa[i].z);
                base[12] = tf32r(pa[i].w);
            }
            {   // B: nt=r>>3, nn=r&7; ks=c4>>3, f=(c4&7)>>2
                const int nt = r >> 3, nn = r & 7;
                const int ks = c4 >> 3, f = (c4 & 7) >> 2;
                uint32_t* base = &Bs[((((nt << 2) + ks) << 6) + (nn << 3)) + f];
                base[0] = tf32r(pb[i].x);
                base[2] = tf32r(pb[i].y);
                base[4] = tf32r(pb[i].z);
                base[6] = tf32r(pb[i].w);
            }
        }
        __syncthreads();

        const bool more = (t + 1 < T);
        if (more) {
#pragma unroll
            for (int i = 0; i < 4; i++) {
                const int qd = tid + i * 256;
                const int r = qd >> 3, c4 = (qd & 7) << 2;
                pa[i] = *(const float4*)(A  + (size_t)(bm + r) * K + (t + 1) * 32 + c4);
                pb[i] = *(const float4*)(Bt + (size_t)(bn + r) * K + (t + 1) * 32 + c4);
            }
        }

        // compute: 4 k-steps x (4 mt x 4 nt) m16n8k8
#pragma unroll
        for (int ks = 0; ks < 4; ks++) {
            uint32_t af[4][4], bf[4][2];
#pragma unroll
            for (int i = 0; i < 4; i++) {
                const int mt = (wm << 2) + i;
                *(uint4*)af[i] = *(const uint4*)&As[((((mt << 2) + ks) << 5) + lane) << 2];
            }
#pragma unroll
            for (int j = 0; j < 4; j++) {
                const int nt = (wn << 2) + j;
                *(uint2*)bf[j] = *(const uint2*)&Bs[((((nt << 2) + ks) << 5) + lane) << 1];
            }
#pragma unroll
            for (int i = 0; i < 4; i++)
#pragma unroll
                for (int j = 0; j < 4; j++)
                    mma_tf32(acc[i][j], af[i], bf[j]);
        }
        __syncthreads();
        if (!more) break;
    }

    // epilogue: warp tile rows bm + wm*64 + i*16 + {g, g+8}, cols bn + wn*32 + j*8 + 2*tg
    const int g  = lane >> 2;
    const int tg = lane & 3;
#pragma unroll
    for (int i = 0; i < 4; i++) {
#pragma unroll
        for (int half = 0; half < 2; half++) {
            const int row = bm + wm * 64 + i * 16 + g + half * 8;
            float* cp = C + (size_t)row * N;
            const float* rp = RES ? (res + (size_t)row * N) : nullptr;
#pragma unroll
            for (int j = 0; j < 4; j++) {
                const int col = bn + wn * 32 + j * 8 + tg * 2;
                float2 o;
                o.x = acc[i][j][half * 2 + 0] + bias[col + 0];
                o.y = acc[i][j][half * 2 + 1] + bias[col + 1];
                if (GELU) {
                    o.x = gelu_exact(o.x);
                    o.y = gelu_exact(o.y);
                }
                if (RES) {
                    const float2 r2 = *(const float2*)(rp + col);
                    o.x += r2.x;
                    o.y += r2.y;
                }
                *(float2*)(cp + col) = o;
            }
        }
    }
}

// ---------------- kernel 4: LayerNorm (row per block) ----------------
__global__ void ln_kernel(const float* __restrict__ in,
                          const float* __restrict__ g,
                          const float* __restrict__ b,
                          float* __restrict__ out) {
    __shared__ float red1[8], red2[8];
    __shared__ float smu, srs;
    const int tid = threadIdx.x;
    const int lane = tid & 31, warp = tid >> 5;
    const size_t row = blockIdx.x;

    float4 val = ((const float4*)(in + row * EMB))[tid];
    float s1 = val.x + val.y + val.z + val.w;
    float s2 = val.x*val.x + val.y*val.y + val.z*val.z + val.w*val.w;
    s1 = warpSum(s1);
    s2 = warpSum(s2);
    if (lane == 0) { red1[warp] = s1; red2[warp] = s2; }
    __syncthreads();
    if (warp == 0) {
        float a = (lane < 8) ? red1[lane] : 0.f;
        float c = (lane < 8) ? red2[lane] : 0.f;
        a = warpSum(a);
        c = warpSum(c);
        if (lane == 0) {
            float mu = a * (1.f / EMB);
            float var = c * (1.f / EMB) - mu * mu;
            smu = mu;
            srs = rsqrtf(var + 1e-5f);
        }
    }
    __syncthreads();
    const float mu = smu, rs = srs;
    float4 g4 = ((const float4*)g)[tid];
    float4 b4 = ((const float4*)b)[tid];
    float4 o;
    o.x = (val.x - mu) * rs * g4.x + b4.x;
    o.y = (val.y - mu) * rs * g4.y + b4.y;
    o.z = (val.z - mu) * rs * g4.z + b4.z;
    o.w = (val.w - mu) * rs * g4.w + b4.w;
    ((float4*)(out + row * EMB))[tid] = o;
}

// ---------------- launch ----------------
extern "C" void kernel_launch(void* const* d_in, const int* in_sizes, int n_in,
                              void* d_out, int out_size) {
    const float* x    = (const float*)d_in[0];
    const float* Wq   = (const float*)d_in[1];
    const float* Wk   = (const float*)d_in[2];
    const float* Wv   = (const float*)d_in[3];
    const float* Wo   = (const float*)d_in[4];
    const float* bo   = (const float*)d_in[5];
    const float* ln1g = (const float*)d_in[6];
    const float* ln1b = (const float*)d_in[7];
    const float* ln2g = (const float*)d_in[8];
    const float* ln2b = (const float*)d_in[9];
    const float* W1   = (const float*)d_in[10];
    const float* b1   = (const float*)d_in[11];
    const float* W2   = (const float*)d_in[12];
    const float* b2   = (const float*)d_in[13];
    float* out = (float*)d_out;

    float *gq, *gk, *gv, *gctx, *gattn, *gan, *gff1, *gwo, *gw1, *gw2;
    cudaGetSymbolAddress((void**)&gq,   g_q);
    cudaGetSymbolAddress((void**)&gk,   g_k);
    cudaGetSymbolAddress((void**)&gv,   g_v);
    cudaGetSymbolAddress((void**)&gctx, g_ctx);
    cudaGetSymbolAddress((void**)&gattn,g_attn);
    cudaGetSymbolAddress((void**)&gan,  g_an);
    cudaGetSymbolAddress((void**)&gff1, g_ff1);
    cudaGetSymbolAddress((void**)&gwo,  g_wo_t);
    cudaGetSymbolAddress((void**)&gw1,  g_w1_t);
    cudaGetSymbolAddress((void**)&gw2,  g_w2_t);

    const int lnqkv_smem = (QKV_ROWS * EMB + 3 * 4096) * sizeof(float); // 80KB
    cudaFuncSetAttribute(ln_qkv_kernel, cudaFuncAttributeMaxDynamicSharedMemorySize, lnqkv_smem);

    // 0) weight transposes: Bt[N][K] from B[K][N]
    transpose_kernel<<<dim3(EMB / 32, EMB / 32), dim3(32, 8)>>>(Wo, gwo, EMB, EMB);
    transpose_kernel<<<dim3(FFN / 32, EMB / 32), dim3(32, 8)>>>(W1, gw1, EMB, FFN);
    transpose_kernel<<<dim3(EMB / 32, FFN / 32), dim3(32, 8)>>>(W2, gw2, FFN, EMB);

    // 1) LN1 + QKV
    ln_qkv_kernel<<<NTOK / QKV_ROWS, 256, lnqkv_smem>>>(x, Wq, Wk, Wv, ln1g, ln1b, gq, gk, gv);

    // 2) attention
    attn_kernel<<<NB * NH * (SEQ / BQ), 128>>>(gq, gk, gv, gctx);

    // 3) attn_out = x + ctx @ Wo + bo            (tf32 mma.sync)
    gemm_mma<false, true><<<dim3(EMB / 128, NTOK / 128), 256>>>(
        gctx, gwo, bo, x, gattn, NTOK, EMB, EMB);

    // 4) LN2
    ln_kernel<<<NTOK, 256>>>(gattn, ln2g, ln2b, gan);

    // 5) ff1 = gelu(an @ W1 + b1)                (tf32 mma.sync)
    gemm_mma<true, false><<<dim3(FFN / 128, NTOK / 128), 256>>>(
        gan, gw1, b1, nullptr, gff1, NTOK, FFN, EMB);

    // 6) out = attn_out + ff1 @ W2 + b2          (tf32 mma.sync)
    gemm_mma<false, true><<<dim3(EMB / 128, NTOK / 128), 256>>>(
        gff1, gw2, b2, gattn, out, NTOK, EMB, FFN);
}

// round 13
// speedup vs baseline: 1.4714x; 1.0004x over previous
#include <cuda_runtime.h>
#include <math.h>
#include <stdint.h>

#define NB 4
#define SEQ 2048
#define EMB 1024
#define NH 16
#define HD 64
#define FFN 4096
#define NTOK (NB*SEQ)      // 8192
#define QKV_ROWS 8
#define ATT_SCALE 0.03125f // 1/sqrt(1024)

typedef unsigned long long u64;

// ---------------- f32x2 packed-math helpers ----------------
__device__ __forceinline__ u64 fma2(u64 a, u64 b, u64 c) {
    u64 d;
    asm("fma.rn.f32x2 %0, %1, %2, %3;" : "=l"(d) : "l"(a), "l"(b), "l"(c));
    return d;
}
__device__ __forceinline__ u64 mul2(u64 a, u64 b) {
    u64 d;
    asm("mul.rn.f32x2 %0, %1, %2;" : "=l"(d) : "l"(a), "l"(b));
    return d;
}
__device__ __forceinline__ u64 add2(u64 a, u64 b) {
    u64 d;
    asm("add.rn.f32x2 %0, %1, %2;" : "=l"(d) : "l"(a), "l"(b));
    return d;
}
__device__ __forceinline__ u64 dup2(float x) {
    u64 d;
    asm("mov.b64 %0, {%1, %1};" : "=l"(d) : "f"(x));
    return d;
}
__device__ __forceinline__ u64 pack2(float lo, float hi) {
    u64 d;
    asm("mov.b64 %0, {%1, %2};" : "=l"(d) : "f"(lo), "f"(hi));
    return d;
}
__device__ __forceinline__ float2 unpk2(u64 v) {
    float2 r;
    asm("mov.b64 {%0, %1}, %2;" : "=f"(r.x), "=f"(r.y) : "l"(v));
    return r;
}
__device__ __forceinline__ u64 d2u(double x) { return __double_as_longlong(x); }

__device__ __forceinline__ uint32_t tf32r(float x) {
    uint32_t y;
    asm("cvt.rna.tf32.f32 %0, %1;" : "=r"(y) : "f"(x));
    return y;
}

// ---------------- scratch (no allocations allowed) ----------------
__device__ float g_q[(size_t)NB*NH*SEQ*HD];
__device__ float g_k[(size_t)NB*NH*SEQ*HD];
__device__ float g_v[(size_t)NB*NH*SEQ*HD];
__device__ float g_ctx[(size_t)NTOK*EMB];
__device__ float g_attn[(size_t)NTOK*EMB];
__device__ float g_an[(size_t)NTOK*EMB];
__device__ float g_ff1[(size_t)NTOK*FFN];
__device__ float g_wo_t[(size_t)EMB*EMB];
__device__ float g_w1_t[(size_t)FFN*EMB];
__device__ float g_w2_t[(size_t)EMB*FFN];

__device__ __forceinline__ float warpSum(float v) {
#pragma unroll
    for (int o = 16; o > 0; o >>= 1) v += __shfl_xor_sync(0xffffffffu, v, o);
    return v;
}

// ---------------- kernel 0: transpose B[K][N] -> Bt[N][K] ----------------
__global__ void transpose_kernel(const float* __restrict__ in, float* __restrict__ out,
                                 int R, int Ccols) {
    __shared__ float ts[32][33];
    const int cb = blockIdx.x * 32, rb = blockIdx.y * 32;
    const int tx = threadIdx.x, ty = threadIdx.y;   // 32 x 8
#pragma unroll
    for (int j = 0; j < 32; j += 8)
        ts[ty + j][tx] = in[(size_t)(rb + ty + j) * Ccols + cb + tx];
    __syncthreads();
#pragma unroll
    for (int j = 0; j < 32; j += 8)
        out[(size_t)(cb + ty + j) * R + rb + tx] = ts[tx][ty + j];
}

// ---------------- kernel 1: LN1 + QKV projections (fused, f32x2) ----------
__global__ void __launch_bounds__(256) ln_qkv_kernel(const float* __restrict__ x,
                              const float* __restrict__ Wq,
                              const float* __restrict__ Wk,
                              const float* __restrict__ Wv,
                              const float* __restrict__ lng,
                              const float* __restrict__ lnb,
                              float* __restrict__ q,
                              float* __restrict__ k,
                              float* __restrict__ v) {
    extern __shared__ float sm[];
    float* xs = sm;                       // QKV_ROWS * 1024
    float* Ws = sm + QKV_ROWS * EMB;      // 3 * 4096

    __shared__ float red1[8], red2[8];
    __shared__ float smu[QKV_ROWS], srs[QKV_ROWS];

    const int tid  = threadIdx.x;
    const int lane = tid & 31;
    const int warp = tid >> 5;
    const int row0 = blockIdx.x * QKV_ROWS;

    for (int i = tid; i < 1024; i += 256) {
        ((float4*)Ws)[i]        = ((const float4*)Wq)[i];
        ((float4*)Ws)[1024 + i] = ((const float4*)Wk)[i];
        ((float4*)Ws)[2048 + i] = ((const float4*)Wv)[i];
    }

    for (int r = 0; r < QKV_ROWS; r++) {
        float4 val = ((const float4*)(x + (size_t)(row0 + r) * EMB))[tid];
        ((float4*)(xs + r * EMB))[tid] = val;
        float s1 = val.x + val.y + val.z + val.w;
        float s2 = val.x*val.x + val.y*val.y + val.z*val.z + val.w*val.w;
        s1 = warpSum(s1);
        s2 = warpSum(s2);
        if (lane == 0) { red1[warp] = s1; red2[warp] = s2; }
        __syncthreads();
        if (warp == 0) {
            float a = (lane < 8) ? red1[lane] : 0.f;
            float c = (lane < 8) ? red2[lane] : 0.f;
            a = warpSum(a);
            c = warpSum(c);
            if (lane == 0) {
                float mu  = a * (1.f / EMB);
                float var = c * (1.f / EMB) - mu * mu;
                smu[r] = mu;
                srs[r] = rsqrtf(var + 1e-5f);
            }
        }
        __syncthreads();
    }

    for (int r = 0; r < QKV_ROWS; r++) {
        float mu = smu[r], rs = srs[r];
        float4 val = ((float4*)(xs + r * EMB))[tid];
        float4 g4  = ((const float4*)lng)[tid];
        float4 b4  = ((const float4*)lnb)[tid];
        val.x = (val.x - mu) * rs * g4.x + b4.x;
        val.y = (val.y - mu) * rs * g4.y + b4.y;
        val.z = (val.z - mu) * rs * g4.z + b4.z;
        val.w = (val.w - mu) * rs * g4.w + b4.w;
        ((float4*)(xs + r * EMB))[tid] = val;
    }
    __syncthreads();

    for (int cc = 0; cc < 2; cc++) {
        const int p = tid + cc * 256;
        const int h = p >> 5;
        const int d = (p & 31) * 2;
        const float* xb = xs + h * HD;
        const float* wqp = Ws + d;
        const float* wkp = Ws + 4096 + d;
        const float* wvp = Ws + 8192 + d;

        u64 acc[3][QKV_ROWS];
#pragma unroll
        for (int w = 0; w < 3; w++)
#pragma unroll
            for (int r = 0; r < QKV_ROWS; r++) acc[w][r] = 0ull;

#pragma unroll 4
        for (int i = 0; i < 64; i++) {
            const u64 wq2 = *(const u64*)(wqp + i * 64);
            const u64 wk2 = *(const u64*)(wkp + i * 64);
            const u64 wv2 = *(const u64*)(wvp + i * 64);
#pragma unroll
            for (int r = 0; r < QKV_ROWS; r++) {
                const u64 ad = dup2(xb[r * EMB + i]);
                acc[0][r] = fma2(ad, wq2, acc[0][r]);
                acc[1][r] = fma2(ad, wk2, acc[1][r]);
                acc[2][r] = fma2(ad, wv2, acc[2][r]);
            }
        }

#pragma unroll
        for (int r = 0; r < QKV_ROWS; r++) {
            const int R = row0 + r;
            const int n = R >> 11;
            const int s = R & (SEQ - 1);
            const size_t base = ((((size_t)n * NH + h) * SEQ) + s) * HD + d;
            float2 fq = unpk2(acc[0][r]);
            float2 fk = unpk2(acc[1][r]);
            float2 fv = unpk2(acc[2][r]);
            *(float2*)(q + base) = fq;
            *(float2*)(k + base) = fk;
            *(float2*)(v + base) = fv;
        }
    }
}

// ---------------- kernel 2: flash-style attention (f32x2) ----------------
#define BQ 128
#define BK 64
__global__ void __launch_bounds__(128, 3) attn_kernel(const float* __restrict__ q,
                                                   const float* __restrict__ k,
                                                   const float* __restrict__ v,
                                                   float* __restrict__ ctx) {
    __shared__ __align__(16) float Ks[BK][HD];
    __shared__ __align__(16) float Vs[BK][HD];

    const int tid = threadIdx.x;
    const int qt  = blockIdx.x & (SEQ / BQ - 1);
    const int nh  = blockIdx.x >> 4;
    const int qi  = qt * BQ + tid;

    const float* qp = q + ((size_t)nh * SEQ + qi) * HD;
    u64 q2[32];
#pragma unroll
    for (int i = 0; i < 16; i++) {
        float4 t4 = ((const float4*)qp)[i];
        q2[2*i+0] = pack2(t4.x * ATT_SCALE, t4.y * ATT_SCALE);
        q2[2*i+1] = pack2(t4.z * ATT_SCALE, t4.w * ATT_SCALE);
    }

    u64 acc[32];
#pragma unroll
    for (int i = 0; i < 32; i++) acc[i] = 0ull;
    float m = -1e30f, l = 0.f;

    const float* kbase = k + (size_t)nh * SEQ * HD;
    const float* vbase = v + (size_t)nh * SEQ * HD;

    for (int t = 0; t < SEQ; t += BK) {
        __syncthreads();
        const float4* ksrc = (const float4*)(kbase + (size_t)t * HD);
        const float4* vsrc = (const float4*)(vbase + (size_t)t * HD);
        float4* kd = (float4*)&Ks[0][0];
        float4* vd = (float4*)&Vs[0][0];
#pragma unroll
        for (int i = 0; i < 8; i++) {
            kd[tid + 128 * i] = ksrc[tid + 128 * i];
            vd[tid + 128 * i] = vsrc[tid + 128 * i];
        }
        __syncthreads();

#pragma unroll 1
        for (int j = 0; j < BK; j++) {
            const double2* kp = (const double2*)&Ks[j][0];
            u64 s2[4] = {0ull, 0ull, 0ull, 0ull};
#pragma unroll
            for (int i = 0; i < 16; i++) {
                double2 kv = kp[i];
                s2[(2*i)   & 3] = fma2(q2[2*i],   d2u(kv.x), s2[(2*i)   & 3]);
                s2[(2*i+1) & 3] = fma2(q2[2*i+1], d2u(kv.y), s2[(2*i+1) & 3]);
            }
            u64 sc = add2(add2(s2[0], s2[1]), add2(s2[2], s2[3]));
            float2 sf = unpk2(sc);
            float s = sf.x + sf.y;

            if (s > m) {
                float c = __expf(m - s);
                l *= c;
                u64 cd = dup2(c);
#pragma unroll
                for (int d2i = 0; d2i < 32; d2i++) acc[d2i] = mul2(acc[d2i], cd);
                m = s;
            }
            float pw = __expf(s - m);
            l += pw;
            const u64 pd = dup2(pw);
            const double2* vp = (const double2*)&Vs[j][0];
#pragma unroll
            for (int i = 0; i < 16; i++) {
                double2 vv = vp[i];
                acc[2*i+0] = fma2(pd, d2u(vv.x), acc[2*i+0]);
                acc[2*i+1] = fma2(pd, d2u(vv.y), acc[2*i+1]);
            }
        }
    }

    const int n = nh >> 4, h = nh & 15;
    float* cp = ctx + (((size_t)(n * SEQ + qi)) * NH + h) * HD;
    const float inv = 1.f / l;
#pragma unroll
    for (int i = 0; i < 16; i++) {
        float2 p0 = unpk2(acc[2*i+0]);
        float2 p1 = unpk2(acc[2*i+1]);
        float4 o;
        o.x = p0.x * inv;
        o.y = p0.y * inv;
        o.z = p1.x * inv;
        o.w = p1.y * inv;
        ((float4*)cp)[i] = o;
    }
}

// ---------------- mma.sync tf32 GEMM (portable PTX, tensor pipe) ----------
// C[M,N] = epi(A[M,K] @ Bt[N,K]^T + bias [+ res])
// BM=128, BN=128, BK=32, 256 threads (8 warps, 2M x 4N), warp tile 64x32.
// m16n8k8 tf32 fragments; smem staged fragment-packed for LDS.128/LDS.64.
__device__ __forceinline__ float gelu_exact(float x) {
    return 0.5f * x * (1.f + erff(x * 0.70710678118654752f));
}

__device__ __forceinline__ void mma_tf32(float* d, const uint32_t* a, const uint32_t* b) {
    asm volatile(
        "mma.sync.aligned.m16n8k8.row.col.f32.tf32.tf32.f32 "
        "{%0, %1, %2, %3}, {%4, %5, %6, %7}, {%8, %9}, {%0, %1, %2, %3};"
        : "+f"(d[0]), "+f"(d[1]), "+f"(d[2]), "+f"(d[3])
        : "r"(a[0]), "r"(a[1]), "r"(a[2]), "r"(a[3]), "r"(b[0]), "r"(b[1]));
}

template <bool GELU, bool RES>
__global__ void __launch_bounds__(256, 1) gemm_mma(const float* __restrict__ A,
                                                   const float* __restrict__ Bt,
                                                   const float* __restrict__ bias,
                                                   const float* __restrict__ res,
                                                   float* __restrict__ C,
                                                   int M, int N, int K) {
    // fragment-packed: As[(mt*4+ks)*32 + lane][4], Bs[(nt*4+ks)*32 + lane][2]
    __shared__ __align__(16) uint32_t As[4096];
    __shared__ __align__(16) uint32_t Bs[4096];

    const int tid  = threadIdx.x;
    const int wid  = tid >> 5;
    const int lane = tid & 31;
    const int wm = wid & 1;          // 2 warps along M
    const int wn = wid >> 1;         // 4 warps along N
    const int bm = blockIdx.y * 128;
    const int bn = blockIdx.x * 128;

    float acc[4][4][4];
#pragma unroll
    for (int i = 0; i < 4; i++)
#pragma unroll
        for (int j = 0; j < 4; j++)
#pragma unroll
            for (int e = 0; e < 4; e++) acc[i][j][e] = 0.f;

    // loader coordinates: 1024 float4 per tile / 256 threads = 4 each
    // q = tid + i*256 -> row r = q>>3, col4 c4 = (q&7)*4
    const int T = K >> 5;

    float4 pa[4], pb[4];
#pragma unroll
    for (int i = 0; i < 4; i++) {
        const int qd = tid + i * 256;
        const int r = qd >> 3, c4 = (qd & 7) << 2;
        pa[i] = *(const float4*)(A  + (size_t)(bm + r) * K + c4);
        pb[i] = *(const float4*)(Bt + (size_t)(bn + r) * K + c4);
    }

    for (int t = 0; ; t++) {
        // stage fragment-packed (with tf32 rounding)
#pragma unroll
        for (int i = 0; i < 4; i++) {
            const int qd = tid + i * 256;
            const int r = qd >> 3, c4 = (qd & 7) << 2;
            {   // A: mt=r>>4, rr=r&15 -> g=rr&7, hi=rr>>3; ks=c4>>3, ch=(c4&7)>>2
                const int mt = r >> 4, rr = r & 15;
                const int g = rr & 7, hi = rr >> 3;
                const int ks = c4 >> 3, ch = (c4 & 7) >> 2;
                const int f = hi + 2 * ch;
                uint32_t* base = &As[(((mt << 2) + ks) << 7) + (g << 4) + f];
                base[0]  = tf32r(pa[i].x);
                base[4]  = tf32r(pa[i].y);
                base[8]  = tf32r(pa[i].z);
                base[12] = tf32r(pa[i].w);
            }
            {   // B: nt=r>>3, nn=r&7; ks=c4>>3, f=(c4&7)>>2
                const int nt = r >> 3, nn = r & 7;
                const int ks = c4 >> 3, f = (c4 & 7) >> 2;
                uint32_t* base = &Bs[((((nt << 2) + ks) << 6) + (nn << 3)) + f];
                base[0] = tf32r(pb[i].x);
                base[2] = tf32r(pb[i].y);
                base[4] = tf32r(pb[i].z);
                base[6] = tf32r(pb[i].w);
            }
        }
        __syncthreads();

        const bool more = (t + 1 < T);
        if (more) {
#pragma unroll
            for (int i = 0; i < 4; i++) {
                const int qd = tid + i * 256;
                const int r = qd >> 3, c4 = (qd & 7) << 2;
                pa[i] = *(const float4*)(A  + (size_t)(bm + r) * K + (t + 1) * 32 + c4);
                pb[i] = *(const float4*)(Bt + (size_t)(bn + r) * K + (t + 1) * 32 + c4);
            }
        }

        // compute: 4 k-steps x (4 mt x 4 nt) m16n8k8
#pragma unroll
        for (int ks = 0; ks < 4; ks++) {
            uint32_t af[4][4], bf[4][2];
#pragma unroll
            for (int i = 0; i < 4; i++) {
                const int mt = (wm << 2) + i;
                *(uint4*)af[i] = *(const uint4*)&As[((((mt << 2) + ks) << 5) + lane) << 2];
            }
#pragma unroll
            for (int j = 0; j < 4; j++) {
                const int nt = (wn << 2) + j;
                *(uint2*)bf[j] = *(const uint2*)&Bs[((((nt << 2) + ks) << 5) + lane) << 1];
            }
#pragma unroll
            for (int i = 0; i < 4; i++)
#pragma unroll
                for (int j = 0; j < 4; j++)
                    mma_tf32(acc[i][j], af[i], bf[j]);
        }
        __syncthreads();
        if (!more) break;
    }

    // epilogue: warp tile rows bm + wm*64 + i*16 + {g, g+8}, cols bn + wn*32 + j*8 + 2*tg
    const int g  = lane >> 2;
    const int tg = lane & 3;
#pragma unroll
    for (int i = 0; i < 4; i++) {
#pragma unroll
        for (int half = 0; half < 2; half++) {
            const int row = bm + wm * 64 + i * 16 + g + half * 8;
            float* cp = C + (size_t)row * N;
            const float* rp = RES ? (res + (size_t)row * N) : nullptr;
#pragma unroll
            for (int j = 0; j < 4; j++) {
                const int col = bn + wn * 32 + j * 8 + tg * 2;
                float2 o;
                o.x = acc[i][j][half * 2 + 0] + bias[col + 0];
                o.y = acc[i][j][half * 2 + 1] + bias[col + 1];
                if (GELU) {
                    o.x = gelu_exact(o.x);
                    o.y = gelu_exact(o.y);
                }
                if (RES) {
                    const float2 r2 = *(const float2*)(rp + col);
                    o.x += r2.x;
                    o.y += r2.y;
                }
                *(float2*)(cp + col) = o;
            }
        }
    }
}

// ---------------- kernel 4: LayerNorm (row per block) ----------------
__global__ void ln_kernel(const float* __restrict__ in,
                          const float* __restrict__ g,
                          const float* __restrict__ b,
                          float* __restrict__ out) {
    __shared__ float red1[8], red2[8];
    __shared__ float smu, srs;
    const int tid = threadIdx.x;
    const int lane = tid & 31, warp = tid >> 5;
    const size_t row = blockIdx.x;

    float4 val = ((const float4*)(in + row * EMB))[tid];
    float s1 = val.x + val.y + val.z + val.w;
    float s2 = val.x*val.x + val.y*val.y + val.z*val.z + val.w*val.w;
    s1 = warpSum(s1);
    s2 = warpSum(s2);
    if (lane == 0) { red1[warp] = s1; red2[warp] = s2; }
    __syncthreads();
    if (warp == 0) {
        float a = (lane < 8) ? red1[lane] : 0.f;
        float c = (lane < 8) ? red2[lane] : 0.f;
        a = warpSum(a);
        c = warpSum(c);
        if (lane == 0) {
            float mu = a * (1.f / EMB);
            float var = c * (1.f / EMB) - mu * mu;
            smu = mu;
            srs = rsqrtf(var + 1e-5f);
        }
    }
    __syncthreads();
    const float mu = smu, rs = srs;
    float4 g4 = ((const float4*)g)[tid];
    float4 b4 = ((const float4*)b)[tid];
    float4 o;
    o.x = (val.x - mu) * rs * g4.x + b4.x;
    o.y = (val.y - mu) * rs * g4.y + b4.y;
    o.z = (val.z - mu) * rs * g4.z + b4.z;
    o.w = (val.w - mu) * rs * g4.w + b4.w;
    ((float4*)(out + row * EMB))[tid] = o;
}

// ---------------- launch ----------------
extern "C" void kernel_launch(void* const* d_in, const int* in_sizes, int n_in,
                              void* d_out, int out_size) {
    const float* x    = (const float*)d_in[0];
    const float* Wq   = (const float*)d_in[1];
    const float* Wk   = (const float*)d_in[2];
    const float* Wv   = (const float*)d_in[3];
    const float* Wo   = (const float*)d_in[4];
    const float* bo   = (const float*)d_in[5];
    const float* ln1g = (const float*)d_in[6];
    const float* ln1b = (const float*)d_in[7];
    const float* ln2g = (const float*)d_in[8];
    const float* ln2b = (const float*)d_in[9];
    const float* W1   = (const float*)d_in[10];
    const float* b1   = (const float*)d_in[11];
    const float* W2   = (const float*)d_in[12];
    const float* b2   = (const float*)d_in[13];
    float* out = (float*)d_out;

    float *gq, *gk, *gv, *gctx, *gattn, *gan, *gff1, *gwo, *gw1, *gw2;
    cudaGetSymbolAddress((void**)&gq,   g_q);
    cudaGetSymbolAddress((void**)&gk,   g_k);
    cudaGetSymbolAddress((void**)&gv,   g_v);
    cudaGetSymbolAddress((void**)&gctx, g_ctx);
    cudaGetSymbolAddress((void**)&gattn,g_attn);
    cudaGetSymbolAddress((void**)&gan,  g_an);
    cudaGetSymbolAddress((void**)&gff1, g_ff1);
    cudaGetSymbolAddress((void**)&gwo,  g_wo_t);
    cudaGetSymbolAddress((void**)&gw1,  g_w1_t);
    cudaGetSymbolAddress((void**)&gw2,  g_w2_t);

    const int lnqkv_smem = (QKV_ROWS * EMB + 3 * 4096) * sizeof(float); // 80KB
    cudaFuncSetAttribute(ln_qkv_kernel, cudaFuncAttributeMaxDynamicSharedMemorySize, lnqkv_smem);

    // 0) weight transposes: Bt[N][K] from B[K][N]
    transpose_kernel<<<dim3(EMB / 32, EMB / 32), dim3(32, 8)>>>(Wo, gwo, EMB, EMB);
    transpose_kernel<<<dim3(FFN / 32, EMB / 32), dim3(32, 8)>>>(W1, gw1, EMB, FFN);
    transpose_kernel<<<dim3(EMB / 32, FFN / 32), dim3(32, 8)>>>(W2, gw2, FFN, EMB);

    // 1) LN1 + QKV
    ln_qkv_kernel<<<NTOK / QKV_ROWS, 256, lnqkv_smem>>>(x, Wq, Wk, Wv, ln1g, ln1b, gq, gk, gv);

    // 2) attention
    attn_kernel<<<NB * NH * (SEQ / BQ), 128>>>(gq, gk, gv, gctx);

    // 3) attn_out = x + ctx @ Wo + bo            (tf32 mma.sync)
    gemm_mma<false, true><<<dim3(EMB / 128, NTOK / 128), 256>>>(
        gctx, gwo, bo, x, gattn, NTOK, EMB, EMB);

    // 4) LN2
    ln_kernel<<<NTOK, 256>>>(gattn, ln2g, ln2b, gan);

    // 5) ff1 = gelu(an @ W1 + b1)                (tf32 mma.sync)
    gemm_mma<true, false><<<dim3(FFN / 128, NTOK / 128), 256>>>(
        gan, gw1, b1, nullptr, gff1, NTOK, FFN, EMB);

    // 6) out = attn_out + ff1 @ W2 + b2          (tf32 mma.sync)
    gemm_mma<false, true><<<dim3(EMB / 128, NTOK / 128), 256>>>(
        gff1, gw2, b2, gattn, out, NTOK, EMB, FFN);
}